// round 10
// baseline (speedup 1.0000x reference)
#include <cuda_runtime.h>
#include <cuda_bf16.h>
#include <cstdint>

// Problem constants (shapes are fixed by the dataset)
#define MAX_N 100000
#define MAX_E 1000000

// Scratch: __device__ globals (no runtime allocation allowed)
__device__ float g_xl[MAX_N * 128];      // raw @ Wl
__device__ float g_xr[MAX_N * 128];      // raw @ Wr
__device__ float g_skip[MAX_N * 128];    // raw @ Ws + bs
__device__ int   g_deg[MAX_N];           // in-degree (excl. self-loop)
__device__ int   g_off[MAX_N];           // CSR offsets
__device__ int   g_cur[MAX_N];           // scatter cursors
__device__ int   g_csr[MAX_E];           // src ids grouped by dst
__device__ int   g_is64;                 // edge_index dtype flag (1 = int64)
// W^T in bf16 hi/lo split, XOR-swizzled [n][128] layout, 3 matrices
__device__ __nv_bfloat16 g_Bth[3 * 128 * 128];
__device__ __nv_bfloat16 g_Btl[3 * 128 * 128];

// ===================== PTX helpers (base ISA only) =========================
__device__ __forceinline__ uint32_t smem_u32(const void* p) {
    uint32_t a;
    asm("{ .reg .u64 t; cvta.to.shared.u64 t, %1; cvt.u32.u64 %0, t; }"
        : "=r"(a) : "l"(p));
    return a;
}
#define LDSM_X4(r0, r1, r2, r3, addr) \
    asm volatile("ldmatrix.sync.aligned.m8n8.x4.shared.b16 {%0,%1,%2,%3}, [%4];" \
                 : "=r"(r0), "=r"(r1), "=r"(r2), "=r"(r3) : "r"(addr))
#define MMA_BF16(d, a, b) \
    asm volatile("mma.sync.aligned.m16n8k16.row.col.f32.bf16.bf16.f32 " \
                 "{%0,%1,%2,%3}, {%4,%5,%6,%7}, {%8,%9}, {%0,%1,%2,%3};" \
                 : "+f"((d)[0]), "+f"((d)[1]), "+f"((d)[2]), "+f"((d)[3]) \
                 : "r"((a)[0]), "r"((a)[1]), "r"((a)[2]), "r"((a)[3]), \
                   "r"((b)[0]), "r"((b)[1]))

// Bijective XOR swizzle within [rows][128] bf16 tile (row stride 256B):
// chunk 0..15 -> (chunk&8) | ((chunk^r)&7); ldmatrix conflict-free.
__device__ __forceinline__ int swz(int r, int k) {
    int c = k >> 3;
    int sc = (c & 8) | ((c ^ r) & 7);
    return r * 128 + sc * 8 + (k & 7);
}

// ======================= dtype detect + edge fetch =========================
__global__ void k_detect(const unsigned int* __restrict__ p) {
    unsigned int v = 0;
    for (int i = threadIdx.x; i < 128; i += 32) v |= p[2 * i + 1];
    v |= __shfl_xor_sync(0xffffffffu, v, 16);
    v |= __shfl_xor_sync(0xffffffffu, v, 8);
    v |= __shfl_xor_sync(0xffffffffu, v, 4);
    v |= __shfl_xor_sync(0xffffffffu, v, 2);
    v |= __shfl_xor_sync(0xffffffffu, v, 1);
    if (threadIdx.x == 0) g_is64 = (v == 0u) ? 1 : 0;
}

__device__ __forceinline__ int fetch_idx(const void* ei, long long pos, int n) {
    int v;
    if (g_is64) v = (int)((const long long*)ei)[pos];
    else        v = ((const int*)ei)[pos];
    return min(max(v, 0), n - 1);
}

// ======================= CSR build (counting sort) =========================
__global__ void k_zero_deg(int n) {
    int i = blockIdx.x * blockDim.x + threadIdx.x;
    if (i < n) g_deg[i] = 0;
}

__global__ void k_hist(const void* __restrict__ ei, int E, int n) {
    int i = blockIdx.x * blockDim.x + threadIdx.x;
    if (i >= E) return;
    int d = fetch_idx(ei, (long long)E + i, n);
    atomicAdd(&g_deg[d], 1);
}

// Single-block exclusive scan over g_deg -> g_off (and g_cur copy)
__global__ void k_scan(int n) {
    __shared__ int part[1024];
    const int t = threadIdx.x;
    const int chunk = (n + 1023) / 1024;
    const int lo = t * chunk;
    const int hi = min(lo + chunk, n);
    int sum = 0;
    for (int i = lo; i < hi; i++) sum += g_deg[i];
    part[t] = sum;
    __syncthreads();
    for (int ofs = 1; ofs < 1024; ofs <<= 1) {
        int v = (t >= ofs) ? part[t - ofs] : 0;
        __syncthreads();
        part[t] += v;
        __syncthreads();
    }
    int base = (t == 0) ? 0 : part[t - 1];
    for (int i = lo; i < hi; i++) {
        g_off[i] = base;
        g_cur[i] = base;
        base += g_deg[i];
    }
}

__global__ void k_scatter(const void* __restrict__ ei, int E, int n) {
    int i = blockIdx.x * blockDim.x + threadIdx.x;
    if (i >= E) return;
    int s = fetch_idx(ei, i, n);
    int d = fetch_idx(ei, (long long)E + i, n);
    int pos = atomicAdd(&g_cur[d], 1);
    g_csr[pos] = s;
}

// ---------------------------------------------------------------------------
// Prep: W^T (=Bt[n][k]) in bf16 hi/lo, XOR-swizzled [128][128] tiles.
// ---------------------------------------------------------------------------
__global__ void k_prep(const float* __restrict__ Wl, const float* __restrict__ Wr,
                       const float* __restrict__ Ws) {
    int i = blockIdx.x * blockDim.x + threadIdx.x;
    if (i >= 3 * 16384) return;
    int m = i >> 14, kk = (i >> 7) & 127, nn = i & 127;
    const float* W = (m == 0) ? Wl : ((m == 1) ? Wr : Ws);
    float v = W[kk * 128 + nn];
    __nv_bfloat16 h = __float2bfloat16(v);
    __nv_bfloat16 l = __float2bfloat16(v - __bfloat162float(h));
    int idx = m * 16384 + swz(nn, kk);
    g_Bth[idx] = h;
    g_Btl[idx] = l;
}

// ---------------------------------------------------------------------------
// Tensor-core GEMM via mma.sync bf16 split (unchanged from R8).
// ---------------------------------------------------------------------------
#define SM_AH 0
#define SM_AL 16384
#define SM_BH 32768
#define SM_BL 65536
#define SM_TOTAL 98304

__global__ void __launch_bounds__(256, 2)
k_gemm_mma(const float* __restrict__ x, const float* __restrict__ tf,
           const float* __restrict__ bs, int n) {
    extern __shared__ char smem[];
    const uint32_t sbase = smem_u32(smem);
    const int tid = threadIdx.x;
    const int row0 = blockIdx.x * 64;

    {
        __nv_bfloat16* sh = reinterpret_cast<__nv_bfloat16*>(smem + SM_AH);
        __nv_bfloat16* sl = reinterpret_cast<__nv_bfloat16*>(smem + SM_AL);
        for (int i = tid; i < 64 * 128; i += 256) {
            int r = i >> 7, k = i & 127;
            int g = row0 + r;
            float v = 0.f;
            if (g < n) v = (k < 126) ? x[g * 126 + k] : tf[g * 2 + (k - 126)];
            __nv_bfloat16 h = __float2bfloat16(v);
            __nv_bfloat16 l = __float2bfloat16(v - __bfloat162float(h));
            int idx = swz(r, k);
            sh[idx] = h;
            sl[idx] = l;
        }
    }

    const int wid = tid >> 5;
    const int lane = tid & 31;
    const int wm = wid >> 1;
    const int wn = wid & 1;
    const int r0 = wm * 16;
    const int c0 = wn * 64;
    const int sub = lane >> 3;
    const int rin = lane & 7;

    for (int which = 0; which < 3; which++) {
        float* out = (which == 0) ? g_xl : ((which == 1) ? g_xr : g_skip);

        {
            const uint4* gh = reinterpret_cast<const uint4*>(&g_Bth[which * 16384]);
            const uint4* gl = reinterpret_cast<const uint4*>(&g_Btl[which * 16384]);
            uint4* sh = reinterpret_cast<uint4*>(smem + SM_BH);
            uint4* sl = reinterpret_cast<uint4*>(smem + SM_BL);
            for (int i = tid; i < 2048; i += 256) { sh[i] = gh[i]; sl[i] = gl[i]; }
        }
        __syncthreads();

        float acc[8][4];
#pragma unroll
        for (int nt = 0; nt < 8; nt++)
#pragma unroll
            for (int q = 0; q < 4; q++) acc[nt][q] = 0.f;

#pragma unroll
        for (int ks = 0; ks < 8; ks++) {
            uint32_t ah[4], al[4], bh[8][2], bl[8][2];
            {
                const int ar = r0 + (sub & 1) * 8 + rin;
                const int ac = ks * 2 + (sub >> 1);
                const uint32_t off =
                    (uint32_t)(ar * 256 + (((ac & 8) | ((ac ^ ar) & 7)) << 4));
                LDSM_X4(ah[0], ah[1], ah[2], ah[3], sbase + SM_AH + off);
                LDSM_X4(al[0], al[1], al[2], al[3], sbase + SM_AL + off);
            }
#pragma unroll
            for (int nt2 = 0; nt2 < 4; nt2++) {
                const int br = c0 + nt2 * 16 + (sub >> 1) * 8 + rin;
                const int bc = ks * 2 + (sub & 1);
                const uint32_t off =
                    (uint32_t)(br * 256 + (((bc & 8) | ((bc ^ br) & 7)) << 4));
                uint32_t q0, q1, q2, q3;
                LDSM_X4(q0, q1, q2, q3, sbase + SM_BH + off);
                bh[nt2 * 2][0] = q0;     bh[nt2 * 2][1] = q1;
                bh[nt2 * 2 + 1][0] = q2; bh[nt2 * 2 + 1][1] = q3;
                LDSM_X4(q0, q1, q2, q3, sbase + SM_BL + off);
                bl[nt2 * 2][0] = q0;     bl[nt2 * 2][1] = q1;
                bl[nt2 * 2 + 1][0] = q2; bl[nt2 * 2 + 1][1] = q3;
            }
#pragma unroll
            for (int nt = 0; nt < 8; nt++) {
                MMA_BF16(acc[nt], ah, bh[nt]);
                MMA_BF16(acc[nt], ah, bl[nt]);
                MMA_BF16(acc[nt], al, bh[nt]);
            }
        }

#pragma unroll
        for (int nt = 0; nt < 8; nt++) {
            const int col = c0 + nt * 8 + (lane & 3) * 2;
            float b0 = 0.f, b1 = 0.f;
            if (which == 2) { b0 = bs[col]; b1 = bs[col + 1]; }
            const int ra = row0 + r0 + (lane >> 2);
            if (ra < n) {
                float2 v = make_float2(acc[nt][0] + b0, acc[nt][1] + b1);
                *reinterpret_cast<float2*>(&out[ra * 128 + col]) = v;
            }
            const int rb = ra + 8;
            if (rb < n) {
                float2 v = make_float2(acc[nt][2] + b0, acc[nt][3] + b1);
                *reinterpret_cast<float2*>(&out[rb * 128 + col]) = v;
            }
        }
        __syncthreads();
    }
}

// ---------------------------------------------------------------------------
// Fused GAT aggregation + readout, one WARP per destination node.
// Edge list = [self-loop] ++ csr[off .. off+deg).  Processed in batches of 8:
// all 8 xl gathers issued before any compute (MLP=8), then 8 compute steps.
// denom/acc in registers; epilogue fused (ELU + skip + Wo + sigmoid).
// ---------------------------------------------------------------------------
__global__ void __launch_bounds__(256)
k_gat(const float* __restrict__ att, const float* __restrict__ bias_gat,
      const float* __restrict__ Wo, const float* __restrict__ bo,
      float* __restrict__ out, int n) {
    const int node = blockIdx.x * 8 + (threadIdx.x >> 5);
    const int lane = threadIdx.x & 31;
    if (node >= n) return;

    const float4 xr4 = *reinterpret_cast<const float4*>(&g_xr[node * 128 + lane * 4]);
    const float4 at4 = *reinterpret_cast<const float4*>(&att[lane * 4]);

    const int off = g_off[node];
    const int deg = g_deg[node];
    const unsigned FULL = 0xffffffffu;

    // First 32 CSR indices via one coalesced load + shuffles
    int si = (lane < deg) ? g_csr[off + lane] : 0;

    float4 acc = make_float4(0.f, 0.f, 0.f, 0.f);
    float denom = 0.f;

    for (int j0 = 0; j0 <= deg; j0 += 8) {
        const int cnt = min(8, deg + 1 - j0);
        float4 xv[8];
        // Issue all gathers first (MLP = 8)
#pragma unroll
        for (int t = 0; t < 8; t++) {
            if (t < cnt) {
                const int j = j0 + t;
                int s;
                if (j == 0)       s = node;                       // self-loop
                else if (j <= 32) s = __shfl_sync(FULL, si, j - 1);
                else              s = g_csr[off + j - 1];
                xv[t] = *reinterpret_cast<const float4*>(&g_xl[s * 128 + lane * 4]);
            }
        }
        // Process
#pragma unroll
        for (int t = 0; t < 8; t++) {
            if (t < cnt) {
                const float4 xl = xv[t];
                float m, p = 0.f;
                m = xl.x + xr4.x; p += (m > 0.f ? m : 0.2f * m) * at4.x;
                m = xl.y + xr4.y; p += (m > 0.f ? m : 0.2f * m) * at4.y;
                m = xl.z + xr4.z; p += (m > 0.f ? m : 0.2f * m) * at4.z;
                m = xl.w + xr4.w; p += (m > 0.f ? m : 0.2f * m) * at4.w;
                p += __shfl_xor_sync(FULL, p, 1);
                p += __shfl_xor_sync(FULL, p, 2);

                const float ee = __expf(p);  // |p| bounded; MUFU path
                denom += ee;
                acc.x += ee * xl.x;
                acc.y += ee * xl.y;
                acc.z += ee * xl.z;
                acc.w += ee * xl.w;
            }
        }
    }

    const float dn = 1.f / (denom + 1e-16f);
    const float4 sk = *reinterpret_cast<const float4*>(&g_skip[node * 128 + lane * 4]);
    const float4 bg = *reinterpret_cast<const float4*>(&bias_gat[lane * 4]);
    const float4 ww = *reinterpret_cast<const float4*>(&Wo[lane * 4]);

    float c, p = 0.f;
    c = acc.x * dn + sk.x + bg.x; c = (c > 0.f) ? c : expm1f(c); p += c * ww.x;
    c = acc.y * dn + sk.y + bg.y; c = (c > 0.f) ? c : expm1f(c); p += c * ww.y;
    c = acc.z * dn + sk.z + bg.z; c = (c > 0.f) ? c : expm1f(c); p += c * ww.z;
    c = acc.w * dn + sk.w + bg.w; c = (c > 0.f) ? c : expm1f(c); p += c * ww.w;

    p += __shfl_xor_sync(FULL, p, 16);
    p += __shfl_xor_sync(FULL, p, 8);
    p += __shfl_xor_sync(FULL, p, 4);
    p += __shfl_xor_sync(FULL, p, 2);
    p += __shfl_xor_sync(FULL, p, 1);

    if (lane == 0) {
        out[node] = 1.f / (1.f + __expf(-(p + bo[0])));
    }
}

// ---------------------------------------------------------------------------
extern "C" void kernel_launch(void* const* d_in, const int* in_sizes, int n_in,
                              void* d_out, int out_size) {
    const float* x   = (const float*)d_in[0];   // [N,126]
    const float* tf  = (const float*)d_in[1];   // [N,2]
    const void*  ei  = d_in[2];                 // [2,E] int32 or int64
    const float* Wl  = (const float*)d_in[3];   // [128,128]
    const float* Wr  = (const float*)d_in[4];
    const float* att = (const float*)d_in[5];   // [8,16]
    const float* bg  = (const float*)d_in[6];   // [128]
    const float* Ws  = (const float*)d_in[7];
    const float* bs  = (const float*)d_in[8];
    const float* Wo  = (const float*)d_in[9];   // [128,1]
    const float* bo  = (const float*)d_in[10];  // [1]
    float* out = (float*)d_out;

    const int n = in_sizes[0] / 126;
    const int E = in_sizes[2] / 2;

    cudaFuncSetAttribute(k_gemm_mma, cudaFuncAttributeMaxDynamicSharedMemorySize,
                         SM_TOTAL);

    k_detect<<<1, 32>>>((const unsigned int*)ei);
    k_zero_deg<<<(n + 255) / 256, 256>>>(n);
    k_prep<<<(3 * 16384 + 255) / 256, 256>>>(Wl, Wr, Ws);

    k_hist<<<(E + 255) / 256, 256>>>(ei, E, n);
    k_scan<<<1, 1024>>>(n);
    k_scatter<<<(E + 255) / 256, 256>>>(ei, E, n);

    k_gemm_mma<<<(n + 63) / 64, 256, SM_TOTAL>>>(x, tf, bs, n);

    k_gat<<<(n + 7) / 8, 256>>>(att, bg, Wo, bo, out, n);
}

// round 11
// speedup vs baseline: 1.3669x; 1.3669x over previous
#include <cuda_runtime.h>
#include <cuda_bf16.h>
#include <cuda_fp16.h>
#include <cstdint>

// Problem constants (shapes are fixed by the dataset)
#define MAX_N 100000
#define MAX_E 1000000
#define MAX_TOT (MAX_N + MAX_E)

// Scratch: __device__ globals (no runtime allocation allowed)
__device__ __half2 g_xl[MAX_N * 64];     // raw @ Wl   (fp16, 2/word)
__device__ __half2 g_xr[MAX_N * 64];     // raw @ Wr   (fp16)
__device__ float   g_skip[MAX_N * 128];  // raw @ Ws + bs  (fp32)
__device__ float   g_agg[MAX_N * 128];   // segment_sum(ee * xl[src]), fp32
__device__ float   g_denom[MAX_N * 8];   // softmax denominators per head
__device__ int     g_is64;               // edge_index dtype flag (1 = int64)
// W^T in bf16 hi/lo split, XOR-swizzled [n][128] layout, 3 matrices
__device__ __nv_bfloat16 g_Bth[3 * 128 * 128];
__device__ __nv_bfloat16 g_Btl[3 * 128 * 128];

// ===================== PTX helpers (base ISA only) =========================
__device__ __forceinline__ uint32_t smem_u32(const void* p) {
    uint32_t a;
    asm("{ .reg .u64 t; cvta.to.shared.u64 t, %1; cvt.u32.u64 %0, t; }"
        : "=r"(a) : "l"(p));
    return a;
}
#define LDSM_X4(r0, r1, r2, r3, addr) \
    asm volatile("ldmatrix.sync.aligned.m8n8.x4.shared.b16 {%0,%1,%2,%3}, [%4];" \
                 : "=r"(r0), "=r"(r1), "=r"(r2), "=r"(r3) : "r"(addr))
#define MMA_BF16(d, a, b) \
    asm volatile("mma.sync.aligned.m16n8k16.row.col.f32.bf16.bf16.f32 " \
                 "{%0,%1,%2,%3}, {%4,%5,%6,%7}, {%8,%9}, {%0,%1,%2,%3};" \
                 : "+f"((d)[0]), "+f"((d)[1]), "+f"((d)[2]), "+f"((d)[3]) \
                 : "r"((a)[0]), "r"((a)[1]), "r"((a)[2]), "r"((a)[3]), \
                   "r"((b)[0]), "r"((b)[1]))

// Bijective XOR swizzle within [rows][128] bf16 tile (row stride 256B):
// chunk 0..15 -> (chunk&8) | ((chunk^r)&7); ldmatrix conflict-free.
__device__ __forceinline__ int swz(int r, int k) {
    int c = k >> 3;
    int sc = (c & 8) | ((c ^ r) & 7);
    return r * 128 + sc * 8 + (k & 7);
}

// ======================= misc small kernels ================================
__global__ void k_detect(const unsigned int* __restrict__ p) {
    unsigned int v = 0;
    for (int i = threadIdx.x; i < 128; i += 32) v |= p[2 * i + 1];
    v |= __shfl_xor_sync(0xffffffffu, v, 16);
    v |= __shfl_xor_sync(0xffffffffu, v, 8);
    v |= __shfl_xor_sync(0xffffffffu, v, 4);
    v |= __shfl_xor_sync(0xffffffffu, v, 2);
    v |= __shfl_xor_sync(0xffffffffu, v, 1);
    if (threadIdx.x == 0) g_is64 = (v == 0u) ? 1 : 0;
}

__device__ __forceinline__ void load_edge(const void* ei, int w, int E, int n,
                                          int& s, int& d) {
    if (w < E) {
        if (g_is64) {
            const long long* e = (const long long*)ei;
            s = (int)e[w]; d = (int)e[E + w];
        } else {
            const int* e = (const int*)ei;
            s = e[w]; d = e[E + w];
        }
        s = min(max(s, 0), n - 1);
        d = min(max(d, 0), n - 1);
    } else {
        s = d = w - E;  // self-loop
    }
}

__global__ void k_zero(int n) {
    int i = blockIdx.x * blockDim.x + threadIdx.x;
    const float4 z = make_float4(0.f, 0.f, 0.f, 0.f);
    int nAgg = n * 32;
    if (i < nAgg) {
        reinterpret_cast<float4*>(g_agg)[i] = z;
    } else if (i < nAgg + n * 2) {
        reinterpret_cast<float4*>(g_denom)[i - nAgg] = z;
    }
}

// ---------------------------------------------------------------------------
// Prep: W^T (=Bt[n][k]) in bf16 hi/lo, XOR-swizzled [128][128] tiles.
// ---------------------------------------------------------------------------
__global__ void k_prep(const float* __restrict__ Wl, const float* __restrict__ Wr,
                       const float* __restrict__ Ws) {
    int i = blockIdx.x * blockDim.x + threadIdx.x;
    if (i >= 3 * 16384) return;
    int m = i >> 14, kk = (i >> 7) & 127, nn = i & 127;
    const float* W = (m == 0) ? Wl : ((m == 1) ? Wr : Ws);
    float v = W[kk * 128 + nn];
    __nv_bfloat16 h = __float2bfloat16(v);
    __nv_bfloat16 l = __float2bfloat16(v - __bfloat162float(h));
    int idx = m * 16384 + swz(nn, kk);
    g_Bth[idx] = h;
    g_Btl[idx] = l;
}

// ---------------------------------------------------------------------------
// Tensor-core GEMM via mma.sync bf16 split (R8 structure).
// Outputs: which 0/1 -> fp16 (g_xl/g_xr), which 2 -> fp32 g_skip (+bias).
// ---------------------------------------------------------------------------
#define SM_AH 0
#define SM_AL 16384
#define SM_BH 32768
#define SM_BL 65536
#define SM_TOTAL 98304

__global__ void __launch_bounds__(256, 2)
k_gemm_mma(const float* __restrict__ x, const float* __restrict__ tf,
           const float* __restrict__ bs, int n) {
    extern __shared__ char smem[];
    const uint32_t sbase = smem_u32(smem);
    const int tid = threadIdx.x;
    const int row0 = blockIdx.x * 64;

    {
        __nv_bfloat16* sh = reinterpret_cast<__nv_bfloat16*>(smem + SM_AH);
        __nv_bfloat16* sl = reinterpret_cast<__nv_bfloat16*>(smem + SM_AL);
        for (int i = tid; i < 64 * 128; i += 256) {
            int r = i >> 7, k = i & 127;
            int g = row0 + r;
            float v = 0.f;
            if (g < n) v = (k < 126) ? x[g * 126 + k] : tf[g * 2 + (k - 126)];
            __nv_bfloat16 h = __float2bfloat16(v);
            __nv_bfloat16 l = __float2bfloat16(v - __bfloat162float(h));
            int idx = swz(r, k);
            sh[idx] = h;
            sl[idx] = l;
        }
    }

    const int wid = tid >> 5;
    const int lane = tid & 31;
    const int wm = wid >> 1;
    const int wn = wid & 1;
    const int r0 = wm * 16;
    const int c0 = wn * 64;
    const int sub = lane >> 3;
    const int rin = lane & 7;

    for (int which = 0; which < 3; which++) {
        {
            const uint4* gh = reinterpret_cast<const uint4*>(&g_Bth[which * 16384]);
            const uint4* gl = reinterpret_cast<const uint4*>(&g_Btl[which * 16384]);
            uint4* sh = reinterpret_cast<uint4*>(smem + SM_BH);
            uint4* sl = reinterpret_cast<uint4*>(smem + SM_BL);
            for (int i = tid; i < 2048; i += 256) { sh[i] = gh[i]; sl[i] = gl[i]; }
        }
        __syncthreads();

        float acc[8][4];
#pragma unroll
        for (int nt = 0; nt < 8; nt++)
#pragma unroll
            for (int q = 0; q < 4; q++) acc[nt][q] = 0.f;

#pragma unroll
        for (int ks = 0; ks < 8; ks++) {
            uint32_t ah[4], al[4], bh[8][2], bl[8][2];
            {
                const int ar = r0 + (sub & 1) * 8 + rin;
                const int ac = ks * 2 + (sub >> 1);
                const uint32_t off =
                    (uint32_t)(ar * 256 + (((ac & 8) | ((ac ^ ar) & 7)) << 4));
                LDSM_X4(ah[0], ah[1], ah[2], ah[3], sbase + SM_AH + off);
                LDSM_X4(al[0], al[1], al[2], al[3], sbase + SM_AL + off);
            }
#pragma unroll
            for (int nt2 = 0; nt2 < 4; nt2++) {
                const int br = c0 + nt2 * 16 + (sub >> 1) * 8 + rin;
                const int bc = ks * 2 + (sub & 1);
                const uint32_t off =
                    (uint32_t)(br * 256 + (((bc & 8) | ((bc ^ br) & 7)) << 4));
                uint32_t q0, q1, q2, q3;
                LDSM_X4(q0, q1, q2, q3, sbase + SM_BH + off);
                bh[nt2 * 2][0] = q0;     bh[nt2 * 2][1] = q1;
                bh[nt2 * 2 + 1][0] = q2; bh[nt2 * 2 + 1][1] = q3;
                LDSM_X4(q0, q1, q2, q3, sbase + SM_BL + off);
                bl[nt2 * 2][0] = q0;     bl[nt2 * 2][1] = q1;
                bl[nt2 * 2 + 1][0] = q2; bl[nt2 * 2 + 1][1] = q3;
            }
#pragma unroll
            for (int nt = 0; nt < 8; nt++) {
                MMA_BF16(acc[nt], ah, bh[nt]);
                MMA_BF16(acc[nt], ah, bl[nt]);
                MMA_BF16(acc[nt], al, bh[nt]);
            }
        }

        // Epilogue: lane l -> rows r0+(l>>2)(+8), cols c0+nt*8+(l&3)*2
#pragma unroll
        for (int nt = 0; nt < 8; nt++) {
            const int col = c0 + nt * 8 + (lane & 3) * 2;   // even
            const int ra = row0 + r0 + (lane >> 2);
            const int rb = ra + 8;
            if (which == 2) {
                const float b0 = bs[col], b1 = bs[col + 1];
                if (ra < n) {
                    float2 v = make_float2(acc[nt][0] + b0, acc[nt][1] + b1);
                    *reinterpret_cast<float2*>(&g_skip[ra * 128 + col]) = v;
                }
                if (rb < n) {
                    float2 v = make_float2(acc[nt][2] + b0, acc[nt][3] + b1);
                    *reinterpret_cast<float2*>(&g_skip[rb * 128 + col]) = v;
                }
            } else {
                __half2* out_h = (which == 0) ? g_xl : g_xr;
                if (ra < n)
                    out_h[ra * 64 + (col >> 1)] = __floats2half2_rn(acc[nt][0], acc[nt][1]);
                if (rb < n)
                    out_h[rb * 64 + (col >> 1)] = __floats2half2_rn(acc[nt][2], acc[nt][3]);
            }
        }
        __syncthreads();
    }
}

// ---------------------------------------------------------------------------
// Fused edge pass, one edge per HALF-warp; fp16 xl/xr (one uint4 per matrix):
//   e[h] = att . lrelu(xl[s]+xr[d]); ee = exp(e);
//   denom[d][h] += ee;   agg[d] += ee * xl[s]  (fp32; normalize in k_final).
// ---------------------------------------------------------------------------
__global__ void k_edge(const void* __restrict__ ei,
                       const float* __restrict__ att, int E, int n) {
    const int gt = blockIdx.x * blockDim.x + threadIdx.x;
    const int w = gt >> 4;
    const int hl = threadIdx.x & 15;
    if (w >= E + n) return;

    int s, d;
    load_edge(ei, w, E, n, s, d);

    const uint4 aU = *reinterpret_cast<const uint4*>(&g_xl[s * 64 + hl * 4]);
    const uint4 bU = *reinterpret_cast<const uint4*>(&g_xr[d * 64 + hl * 4]);
    const float4 t0 = *reinterpret_cast<const float4*>(&att[hl * 8]);
    const float4 t1 = *reinterpret_cast<const float4*>(&att[hl * 8 + 4]);

    const __half2* ah = reinterpret_cast<const __half2*>(&aU);
    const __half2* bh = reinterpret_cast<const __half2*>(&bU);
    const float2 a01 = __half22float2(ah[0]);
    const float2 a23 = __half22float2(ah[1]);
    const float2 a45 = __half22float2(ah[2]);
    const float2 a67 = __half22float2(ah[3]);
    const float2 b01 = __half22float2(bh[0]);
    const float2 b23 = __half22float2(bh[1]);
    const float2 b45 = __half22float2(bh[2]);
    const float2 b67 = __half22float2(bh[3]);

    float m, p = 0.f;
    m = a01.x + b01.x; p += (m > 0.f ? m : 0.2f * m) * t0.x;
    m = a01.y + b01.y; p += (m > 0.f ? m : 0.2f * m) * t0.y;
    m = a23.x + b23.x; p += (m > 0.f ? m : 0.2f * m) * t0.z;
    m = a23.y + b23.y; p += (m > 0.f ? m : 0.2f * m) * t0.w;
    m = a45.x + b45.x; p += (m > 0.f ? m : 0.2f * m) * t1.x;
    m = a45.y + b45.y; p += (m > 0.f ? m : 0.2f * m) * t1.y;
    m = a67.x + b67.x; p += (m > 0.f ? m : 0.2f * m) * t1.z;
    m = a67.y + b67.y; p += (m > 0.f ? m : 0.2f * m) * t1.w;

    // head h = hl>>1 spans lanes {2h, 2h+1}
    p += __shfl_xor_sync(0xffffffffu, p, 1);

    const float ex = __expf(p);   // softmax-max dropped: |e| bounded

    if ((hl & 1) == 0) {
        atomicAdd(&g_denom[d * 8 + (hl >> 1)], ex);
    }

    float* p0 = &g_agg[d * 128 + hl * 8];
    asm volatile("red.global.add.v4.f32 [%0], {%1, %2, %3, %4};"
                 :: "l"(p0), "f"(ex * a01.x), "f"(ex * a01.y),
                    "f"(ex * a23.x), "f"(ex * a23.y) : "memory");
    asm volatile("red.global.add.v4.f32 [%0], {%1, %2, %3, %4};"
                 :: "l"(p0 + 4), "f"(ex * a45.x), "f"(ex * a45.y),
                    "f"(ex * a67.x), "f"(ex * a67.y) : "memory");
}

// ---------------------------------------------------------------------------
// Final: out = sigmoid( elu(agg/denom + bias_gat + skip) @ Wo + bo )
// ---------------------------------------------------------------------------
__global__ void k_final(const float* __restrict__ bias_gat,
                        const float* __restrict__ Wo,
                        const float* __restrict__ bo,
                        float* __restrict__ out, int n) {
    const int w = (blockIdx.x * blockDim.x + threadIdx.x) >> 5;
    const int lane = threadIdx.x & 31;
    if (w >= n) return;

    const int base = w * 128 + lane * 4;
    const float4 g  = *reinterpret_cast<const float4*>(&g_agg[base]);
    const float4 s  = *reinterpret_cast<const float4*>(&g_skip[base]);
    const float4 bg = *reinterpret_cast<const float4*>(&bias_gat[lane * 4]);
    const float4 ww = *reinterpret_cast<const float4*>(&Wo[lane * 4]);

    const float dn = 1.f / (g_denom[w * 8 + (lane >> 2)] + 1e-16f);

    float c, p = 0.f;
    c = g.x * dn + s.x + bg.x; c = (c > 0.f) ? c : expm1f(c); p += c * ww.x;
    c = g.y * dn + s.y + bg.y; c = (c > 0.f) ? c : expm1f(c); p += c * ww.y;
    c = g.z * dn + s.z + bg.z; c = (c > 0.f) ? c : expm1f(c); p += c * ww.z;
    c = g.w * dn + s.w + bg.w; c = (c > 0.f) ? c : expm1f(c); p += c * ww.w;

    p += __shfl_xor_sync(0xffffffffu, p, 16);
    p += __shfl_xor_sync(0xffffffffu, p, 8);
    p += __shfl_xor_sync(0xffffffffu, p, 4);
    p += __shfl_xor_sync(0xffffffffu, p, 2);
    p += __shfl_xor_sync(0xffffffffu, p, 1);

    if (lane == 0) {
        out[w] = 1.f / (1.f + expf(-(p + bo[0])));
    }
}

// ---------------------------------------------------------------------------
extern "C" void kernel_launch(void* const* d_in, const int* in_sizes, int n_in,
                              void* d_out, int out_size) {
    const float* x   = (const float*)d_in[0];   // [N,126]
    const float* tf  = (const float*)d_in[1];   // [N,2]
    const void*  ei  = d_in[2];                 // [2,E] int32 or int64
    const float* Wl  = (const float*)d_in[3];   // [128,128]
    const float* Wr  = (const float*)d_in[4];
    const float* att = (const float*)d_in[5];   // [8,16]
    const float* bg  = (const float*)d_in[6];   // [128]
    const float* Ws  = (const float*)d_in[7];
    const float* bs  = (const float*)d_in[8];
    const float* Wo  = (const float*)d_in[9];   // [128,1]
    const float* bo  = (const float*)d_in[10];  // [1]
    float* out = (float*)d_out;

    const int n = in_sizes[0] / 126;
    const int E = in_sizes[2] / 2;
    const int tot = E + n;

    cudaFuncSetAttribute(k_gemm_mma, cudaFuncAttributeMaxDynamicSharedMemorySize,
                         SM_TOTAL);

    k_detect<<<1, 32>>>((const unsigned int*)ei);
    k_zero<<<(n * 34 + 255) / 256, 256>>>(n);
    k_prep<<<(3 * 16384 + 255) / 256, 256>>>(Wl, Wr, Ws);

    k_gemm_mma<<<(n + 63) / 64, 256, SM_TOTAL>>>(x, tf, bs, n);

    k_edge<<<(tot + 15) / 16, 256>>>(ei, att, E, n);
    k_final<<<(n + 7) / 8, 256>>>(bg, Wo, bo, out, n);
}

// round 12
// speedup vs baseline: 1.4849x; 1.0863x over previous
#include <cuda_runtime.h>
#include <cuda_fp16.h>
#include <cstdint>

// Problem constants (shapes are fixed by the dataset)
#define MAX_N 100000
#define MAX_E 1000000
#define MAX_TOT (MAX_N + MAX_E)

// Scratch: __device__ globals (no runtime allocation allowed)
__device__ __half2 g_xl[MAX_N * 64];     // raw @ Wl   (fp16, 2/word)
__device__ __half2 g_xr[MAX_N * 64];     // raw @ Wr   (fp16)
__device__ float   g_skip[MAX_N * 128];  // raw @ Ws + bs  (fp32)
__device__ float   g_agg[MAX_N * 128];   // segment_sum(ee * xl[src]), fp32
__device__ float   g_denom[MAX_N * 8];   // softmax denominators per head
__device__ int     g_is64;               // edge_index dtype flag (1 = int64)
// W^T fp16: hi for all 3 matrices, lo only for Ws (skip path, 3-product split)
__device__ __half g_Bh16[3 * 128 * 128];
__device__ __half g_Bl16[128 * 128];

// ===================== PTX helpers (base ISA only) =========================
__device__ __forceinline__ uint32_t smem_u32(const void* p) {
    uint32_t a;
    asm("{ .reg .u64 t; cvta.to.shared.u64 t, %1; cvt.u32.u64 %0, t; }"
        : "=r"(a) : "l"(p));
    return a;
}
#define LDSM_X4(r0, r1, r2, r3, addr) \
    asm volatile("ldmatrix.sync.aligned.m8n8.x4.shared.b16 {%0,%1,%2,%3}, [%4];" \
                 : "=r"(r0), "=r"(r1), "=r"(r2), "=r"(r3) : "r"(addr))
#define MMA_F16(d, a, b) \
    asm volatile("mma.sync.aligned.m16n8k16.row.col.f32.f16.f16.f32 " \
                 "{%0,%1,%2,%3}, {%4,%5,%6,%7}, {%8,%9}, {%0,%1,%2,%3};" \
                 : "+f"((d)[0]), "+f"((d)[1]), "+f"((d)[2]), "+f"((d)[3]) \
                 : "r"((a)[0]), "r"((a)[1]), "r"((a)[2]), "r"((a)[3]), \
                   "r"((b)[0]), "r"((b)[1]))

// Bijective XOR swizzle within [rows][128] half tile (row stride 256B):
// chunk 0..15 -> (chunk&8) | ((chunk^r)&7); ldmatrix conflict-free.
__device__ __forceinline__ int swz(int r, int k) {
    int c = k >> 3;
    int sc = (c & 8) | ((c ^ r) & 7);
    return r * 128 + sc * 8 + (k & 7);
}

// ======================= misc small kernels ================================
__global__ void k_detect(const unsigned int* __restrict__ p) {
    unsigned int v = 0;
    for (int i = threadIdx.x; i < 128; i += 32) v |= p[2 * i + 1];
    v |= __shfl_xor_sync(0xffffffffu, v, 16);
    v |= __shfl_xor_sync(0xffffffffu, v, 8);
    v |= __shfl_xor_sync(0xffffffffu, v, 4);
    v |= __shfl_xor_sync(0xffffffffu, v, 2);
    v |= __shfl_xor_sync(0xffffffffu, v, 1);
    if (threadIdx.x == 0) g_is64 = (v == 0u) ? 1 : 0;
}

__device__ __forceinline__ void load_edge(const void* ei, int w, int E, int n,
                                          int& s, int& d) {
    if (w < E) {
        if (g_is64) {
            const long long* e = (const long long*)ei;
            s = (int)e[w]; d = (int)e[E + w];
        } else {
            const int* e = (const int*)ei;
            s = e[w]; d = e[E + w];
        }
        s = min(max(s, 0), n - 1);
        d = min(max(d, 0), n - 1);
    } else {
        s = d = w - E;  // self-loop
    }
}

__global__ void k_zero(int n) {
    int i = blockIdx.x * blockDim.x + threadIdx.x;
    const float4 z = make_float4(0.f, 0.f, 0.f, 0.f);
    int nAgg = n * 32;
    if (i < nAgg) {
        reinterpret_cast<float4*>(g_agg)[i] = z;
    } else if (i < nAgg + n * 2) {
        reinterpret_cast<float4*>(g_denom)[i - nAgg] = z;
    }
}

// ---------------------------------------------------------------------------
// Prep: W^T (=Bt[n][k]) in fp16, XOR-swizzled [128][128] tiles.
// hi for all three; lo residual only for Ws (m=2).
// ---------------------------------------------------------------------------
__global__ void k_prep(const float* __restrict__ Wl, const float* __restrict__ Wr,
                       const float* __restrict__ Ws) {
    int i = blockIdx.x * blockDim.x + threadIdx.x;
    if (i >= 3 * 16384) return;
    int m = i >> 14, kk = (i >> 7) & 127, nn = i & 127;
    const float* W = (m == 0) ? Wl : ((m == 1) ? Wr : Ws);
    float v = W[kk * 128 + nn];
    __half h = __float2half(v);
    int idx = swz(nn, kk);
    g_Bh16[m * 16384 + idx] = h;
    if (m == 2) g_Bl16[idx] = __float2half(v - __half2float(h));
}

// ---------------------------------------------------------------------------
// Mixed-precision tensor-core GEMM (mma.sync fp16):
//   which 0/1 (xl, xr):  single product Ah*Bh        (feeds attention; the
//                        fp16 input error ~7e-4/elem attenuates ~13x to final)
//   which 2   (skip)  :  3-product fp16 hi/lo split  (feeds output directly)
// Block: 64 rows x 128 cols, 256 threads (8 warps = 4m x 2n), A staged once.
// smem 96KB -> 2 blocks/SM.
// ---------------------------------------------------------------------------
#define SM_AH 0
#define SM_AL 16384
#define SM_BH 32768
#define SM_BL 65536
#define SM_TOTAL 98304

__global__ void __launch_bounds__(256, 2)
k_gemm_mma(const float* __restrict__ x, const float* __restrict__ tf,
           const float* __restrict__ bs, int n) {
    extern __shared__ char smem[];
    const uint32_t sbase = smem_u32(smem);
    const int tid = threadIdx.x;
    const int row0 = blockIdx.x * 64;

    // Stage A rows (fp32 coalesced) -> fp16 hi/lo, swizzled
    {
        __half* sh = reinterpret_cast<__half*>(smem + SM_AH);
        __half* sl = reinterpret_cast<__half*>(smem + SM_AL);
        for (int i = tid; i < 64 * 128; i += 256) {
            int r = i >> 7, k = i & 127;
            int g = row0 + r;
            float v = 0.f;
            if (g < n) v = (k < 126) ? x[g * 126 + k] : tf[g * 2 + (k - 126)];
            __half h = __float2half(v);
            int idx = swz(r, k);
            sh[idx] = h;
            sl[idx] = __float2half(v - __half2float(h));
        }
    }

    const int wid = tid >> 5;
    const int lane = tid & 31;
    const int wm = wid >> 1;
    const int wn = wid & 1;
    const int r0 = wm * 16;
    const int c0 = wn * 64;
    const int sub = lane >> 3;
    const int rin = lane & 7;

    for (int which = 0; which < 3; which++) {
        // Copy swizzled Bt images (L2-hot) into smem — byte copy
        if (which < 2) {
            const uint4* gh = reinterpret_cast<const uint4*>(&g_Bh16[which * 16384]);
            uint4* sh = reinterpret_cast<uint4*>(smem + SM_BH);
            for (int i = tid; i < 2048; i += 256) sh[i] = gh[i];
        } else {
            const uint4* gh = reinterpret_cast<const uint4*>(&g_Bh16[2 * 16384]);
            const uint4* gl = reinterpret_cast<const uint4*>(g_Bl16);
            uint4* sh = reinterpret_cast<uint4*>(smem + SM_BH);
            uint4* sl = reinterpret_cast<uint4*>(smem + SM_BL);
            for (int i = tid; i < 2048; i += 256) { sh[i] = gh[i]; sl[i] = gl[i]; }
        }
        __syncthreads();

        float acc[8][4];
#pragma unroll
        for (int nt = 0; nt < 8; nt++)
#pragma unroll
            for (int q = 0; q < 4; q++) acc[nt][q] = 0.f;

        if (which < 2) {
            // ---- light mainloop: 1 A-LDSM + 4 B-LDSM, 8 MMA per ks ----
#pragma unroll
            for (int ks = 0; ks < 8; ks++) {
                uint32_t ah[4], bh[8][2];
                {
                    const int ar = r0 + (sub & 1) * 8 + rin;
                    const int ac = ks * 2 + (sub >> 1);
                    const uint32_t off =
                        (uint32_t)(ar * 256 + (((ac & 8) | ((ac ^ ar) & 7)) << 4));
                    LDSM_X4(ah[0], ah[1], ah[2], ah[3], sbase + SM_AH + off);
                }
#pragma unroll
                for (int nt2 = 0; nt2 < 4; nt2++) {
                    const int br = c0 + nt2 * 16 + (sub >> 1) * 8 + rin;
                    const int bc = ks * 2 + (sub & 1);
                    const uint32_t off =
                        (uint32_t)(br * 256 + (((bc & 8) | ((bc ^ br) & 7)) << 4));
                    uint32_t q0, q1, q2, q3;
                    LDSM_X4(q0, q1, q2, q3, sbase + SM_BH + off);
                    bh[nt2 * 2][0] = q0;     bh[nt2 * 2][1] = q1;
                    bh[nt2 * 2 + 1][0] = q2; bh[nt2 * 2 + 1][1] = q3;
                }
#pragma unroll
                for (int nt = 0; nt < 8; nt++) MMA_F16(acc[nt], ah, bh[nt]);
            }
        } else {
            // ---- full split mainloop: Ah*Bh + Ah*Bl + Al*Bh ----
#pragma unroll
            for (int ks = 0; ks < 8; ks++) {
                uint32_t ah[4], al[4], bh[8][2], bl[8][2];
                {
                    const int ar = r0 + (sub & 1) * 8 + rin;
                    const int ac = ks * 2 + (sub >> 1);
                    const uint32_t off =
                        (uint32_t)(ar * 256 + (((ac & 8) | ((ac ^ ar) & 7)) << 4));
                    LDSM_X4(ah[0], ah[1], ah[2], ah[3], sbase + SM_AH + off);
                    LDSM_X4(al[0], al[1], al[2], al[3], sbase + SM_AL + off);
                }
#pragma unroll
                for (int nt2 = 0; nt2 < 4; nt2++) {
                    const int br = c0 + nt2 * 16 + (sub >> 1) * 8 + rin;
                    const int bc = ks * 2 + (sub & 1);
                    const uint32_t off =
                        (uint32_t)(br * 256 + (((bc & 8) | ((bc ^ br) & 7)) << 4));
                    uint32_t q0, q1, q2, q3;
                    LDSM_X4(q0, q1, q2, q3, sbase + SM_BH + off);
                    bh[nt2 * 2][0] = q0;     bh[nt2 * 2][1] = q1;
                    bh[nt2 * 2 + 1][0] = q2; bh[nt2 * 2 + 1][1] = q3;
                    LDSM_X4(q0, q1, q2, q3, sbase + SM_BL + off);
                    bl[nt2 * 2][0] = q0;     bl[nt2 * 2][1] = q1;
                    bl[nt2 * 2 + 1][0] = q2; bl[nt2 * 2 + 1][1] = q3;
                }
#pragma unroll
                for (int nt = 0; nt < 8; nt++) {
                    MMA_F16(acc[nt], ah, bh[nt]);
                    MMA_F16(acc[nt], ah, bl[nt]);
                    MMA_F16(acc[nt], al, bh[nt]);
                }
            }
        }

        // Epilogue: lane l -> rows r0+(l>>2)(+8), cols c0+nt*8+(l&3)*2
#pragma unroll
        for (int nt = 0; nt < 8; nt++) {
            const int col = c0 + nt * 8 + (lane & 3) * 2;   // even
            const int ra = row0 + r0 + (lane >> 2);
            const int rb = ra + 8;
            if (which == 2) {
                const float b0 = bs[col], b1 = bs[col + 1];
                if (ra < n) {
                    float2 v = make_float2(acc[nt][0] + b0, acc[nt][1] + b1);
                    *reinterpret_cast<float2*>(&g_skip[ra * 128 + col]) = v;
                }
                if (rb < n) {
                    float2 v = make_float2(acc[nt][2] + b0, acc[nt][3] + b1);
                    *reinterpret_cast<float2*>(&g_skip[rb * 128 + col]) = v;
                }
            } else {
                __half2* out_h = (which == 0) ? g_xl : g_xr;
                if (ra < n)
                    out_h[ra * 64 + (col >> 1)] = __floats2half2_rn(acc[nt][0], acc[nt][1]);
                if (rb < n)
                    out_h[rb * 64 + (col >> 1)] = __floats2half2_rn(acc[nt][2], acc[nt][3]);
            }
        }
        __syncthreads();
    }
}

// ---------------------------------------------------------------------------
// Fused edge pass, one edge per HALF-warp; fp16 xl/xr (one uint4 per matrix):
//   e[h] = att . lrelu(xl[s]+xr[d]); ee = exp(e);
//   denom[d][h] += ee;   agg[d] += ee * xl[s]  (fp32; normalize in k_final).
// ---------------------------------------------------------------------------
__global__ void k_edge(const void* __restrict__ ei,
                       const float* __restrict__ att, int E, int n) {
    const int gt = blockIdx.x * blockDim.x + threadIdx.x;
    const int w = gt >> 4;
    const int hl = threadIdx.x & 15;
    if (w >= E + n) return;

    int s, d;
    load_edge(ei, w, E, n, s, d);

    const uint4 aU = *reinterpret_cast<const uint4*>(&g_xl[s * 64 + hl * 4]);
    const uint4 bU = *reinterpret_cast<const uint4*>(&g_xr[d * 64 + hl * 4]);
    const float4 t0 = *reinterpret_cast<const float4*>(&att[hl * 8]);
    const float4 t1 = *reinterpret_cast<const float4*>(&att[hl * 8 + 4]);

    const __half2* ah = reinterpret_cast<const __half2*>(&aU);
    const __half2* bh = reinterpret_cast<const __half2*>(&bU);
    const float2 a01 = __half22float2(ah[0]);
    const float2 a23 = __half22float2(ah[1]);
    const float2 a45 = __half22float2(ah[2]);
    const float2 a67 = __half22float2(ah[3]);
    const float2 b01 = __half22float2(bh[0]);
    const float2 b23 = __half22float2(bh[1]);
    const float2 b45 = __half22float2(bh[2]);
    const float2 b67 = __half22float2(bh[3]);

    float m, p = 0.f;
    m = a01.x + b01.x; p += (m > 0.f ? m : 0.2f * m) * t0.x;
    m = a01.y + b01.y; p += (m > 0.f ? m : 0.2f * m) * t0.y;
    m = a23.x + b23.x; p += (m > 0.f ? m : 0.2f * m) * t0.z;
    m = a23.y + b23.y; p += (m > 0.f ? m : 0.2f * m) * t0.w;
    m = a45.x + b45.x; p += (m > 0.f ? m : 0.2f * m) * t1.x;
    m = a45.y + b45.y; p += (m > 0.f ? m : 0.2f * m) * t1.y;
    m = a67.x + b67.x; p += (m > 0.f ? m : 0.2f * m) * t1.z;
    m = a67.y + b67.y; p += (m > 0.f ? m : 0.2f * m) * t1.w;

    // head h = hl>>1 spans lanes {2h, 2h+1}
    p += __shfl_xor_sync(0xffffffffu, p, 1);

    const float ex = __expf(p);   // softmax-max dropped: |e| bounded

    if ((hl & 1) == 0) {
        atomicAdd(&g_denom[d * 8 + (hl >> 1)], ex);
    }

    float* p0 = &g_agg[d * 128 + hl * 8];
    asm volatile("red.global.add.v4.f32 [%0], {%1, %2, %3, %4};"
                 :: "l"(p0), "f"(ex * a01.x), "f"(ex * a01.y),
                    "f"(ex * a23.x), "f"(ex * a23.y) : "memory");
    asm volatile("red.global.add.v4.f32 [%0], {%1, %2, %3, %4};"
                 :: "l"(p0 + 4), "f"(ex * a45.x), "f"(ex * a45.y),
                    "f"(ex * a67.x), "f"(ex * a67.y) : "memory");
}

// ---------------------------------------------------------------------------
// Final: out = sigmoid( elu(agg/denom + bias_gat + skip) @ Wo + bo )
// ---------------------------------------------------------------------------
__global__ void k_final(const float* __restrict__ bias_gat,
                        const float* __restrict__ Wo,
                        const float* __restrict__ bo,
                        float* __restrict__ out, int n) {
    const int w = (blockIdx.x * blockDim.x + threadIdx.x) >> 5;
    const int lane = threadIdx.x & 31;
    if (w >= n) return;

    const int base = w * 128 + lane * 4;
    const float4 g  = *reinterpret_cast<const float4*>(&g_agg[base]);
    const float4 s  = *reinterpret_cast<const float4*>(&g_skip[base]);
    const float4 bg = *reinterpret_cast<const float4*>(&bias_gat[lane * 4]);
    const float4 ww = *reinterpret_cast<const float4*>(&Wo[lane * 4]);

    const float dn = 1.f / (g_denom[w * 8 + (lane >> 2)] + 1e-16f);

    float c, p = 0.f;
    c = g.x * dn + s.x + bg.x; c = (c > 0.f) ? c : expm1f(c); p += c * ww.x;
    c = g.y * dn + s.y + bg.y; c = (c > 0.f) ? c : expm1f(c); p += c * ww.y;
    c = g.z * dn + s.z + bg.z; c = (c > 0.f) ? c : expm1f(c); p += c * ww.z;
    c = g.w * dn + s.w + bg.w; c = (c > 0.f) ? c : expm1f(c); p += c * ww.w;

    p += __shfl_xor_sync(0xffffffffu, p, 16);
    p += __shfl_xor_sync(0xffffffffu, p, 8);
    p += __shfl_xor_sync(0xffffffffu, p, 4);
    p += __shfl_xor_sync(0xffffffffu, p, 2);
    p += __shfl_xor_sync(0xffffffffu, p, 1);

    if (lane == 0) {
        out[w] = 1.f / (1.f + expf(-(p + bo[0])));
    }
}

// ---------------------------------------------------------------------------
extern "C" void kernel_launch(void* const* d_in, const int* in_sizes, int n_in,
                              void* d_out, int out_size) {
    const float* x   = (const float*)d_in[0];   // [N,126]
    const float* tf  = (const float*)d_in[1];   // [N,2]
    const void*  ei  = d_in[2];                 // [2,E] int32 or int64
    const float* Wl  = (const float*)d_in[3];   // [128,128]
    const float* Wr  = (const float*)d_in[4];
    const float* att = (const float*)d_in[5];   // [8,16]
    const float* bg  = (const float*)d_in[6];   // [128]
    const float* Ws  = (const float*)d_in[7];
    const float* bs  = (const float*)d_in[8];
    const float* Wo  = (const float*)d_in[9];   // [128,1]
    const float* bo  = (const float*)d_in[10];  // [1]
    float* out = (float*)d_out;

    const int n = in_sizes[0] / 126;
    const int E = in_sizes[2] / 2;
    const int tot = E + n;

    cudaFuncSetAttribute(k_gemm_mma, cudaFuncAttributeMaxDynamicSharedMemorySize,
                         SM_TOTAL);

    k_detect<<<1, 32>>>((const unsigned int*)ei);
    k_zero<<<(n * 34 + 255) / 256, 256>>>(n);
    k_prep<<<(3 * 16384 + 255) / 256, 256>>>(Wl, Wr, Ws);

    k_gemm_mma<<<(n + 63) / 64, 256, SM_TOTAL>>>(x, tf, bs, n);

    k_edge<<<(tot + 15) / 16, 256>>>(ei, att, E, n);
    k_final<<<(n + 7) / 8, 256>>>(bg, Wo, bo, out, n);
}

// round 13
// speedup vs baseline: 1.6553x; 1.1147x over previous
#include <cuda_runtime.h>
#include <cuda_fp16.h>
#include <cstdint>

// Problem constants (shapes are fixed by the dataset)
#define MAX_N 100000
#define MAX_E 1000000
#define MAX_TOT (MAX_N + MAX_E)

// Scratch: __device__ globals (no runtime allocation allowed)
__device__ __half2 g_xl[MAX_N * 64];     // raw @ Wl   (fp16, 2/word)
__device__ __half2 g_xr[MAX_N * 64];     // raw @ Wr   (fp16)
__device__ float   g_skip[MAX_N * 128];  // raw @ Ws + bs  (fp32)
__device__ float   g_agg[MAX_N * 128];   // segment_sum(ee * xl[src]), fp32
__device__ float   g_denom[MAX_N * 8];   // softmax denominators per head
__device__ int     g_is64;               // edge_index dtype flag (1 = int64)
// W^T fp16 (hi only), XOR-swizzled [n][128] layout, 3 matrices
__device__ __half g_Bh16[3 * 128 * 128];

// ===================== PTX helpers (base ISA only) =========================
__device__ __forceinline__ uint32_t smem_u32(const void* p) {
    uint32_t a;
    asm("{ .reg .u64 t; cvta.to.shared.u64 t, %1; cvt.u32.u64 %0, t; }"
        : "=r"(a) : "l"(p));
    return a;
}
#define LDSM_X4(r0, r1, r2, r3, addr) \
    asm volatile("ldmatrix.sync.aligned.m8n8.x4.shared.b16 {%0,%1,%2,%3}, [%4];" \
                 : "=r"(r0), "=r"(r1), "=r"(r2), "=r"(r3) : "r"(addr))
#define MMA_F16(d, a, b0v, b1v) \
    asm volatile("mma.sync.aligned.m16n8k16.row.col.f32.f16.f16.f32 " \
                 "{%0,%1,%2,%3}, {%4,%5,%6,%7}, {%8,%9}, {%0,%1,%2,%3};" \
                 : "+f"((d)[0]), "+f"((d)[1]), "+f"((d)[2]), "+f"((d)[3]) \
                 : "r"((a)[0]), "r"((a)[1]), "r"((a)[2]), "r"((a)[3]), \
                   "r"(b0v), "r"(b1v))

// Bijective XOR swizzle within [rows][128] half tile (row stride 256B):
// chunk 0..15 -> (chunk&8) | ((chunk^r)&7); ldmatrix conflict-free.
__device__ __forceinline__ int swz(int r, int k) {
    int c = k >> 3;
    int sc = (c & 8) | ((c ^ r) & 7);
    return r * 128 + sc * 8 + (k & 7);
}

// ======================= misc small kernels ================================
__global__ void k_detect(const unsigned int* __restrict__ p) {
    unsigned int v = 0;
    for (int i = threadIdx.x; i < 128; i += 32) v |= p[2 * i + 1];
    v |= __shfl_xor_sync(0xffffffffu, v, 16);
    v |= __shfl_xor_sync(0xffffffffu, v, 8);
    v |= __shfl_xor_sync(0xffffffffu, v, 4);
    v |= __shfl_xor_sync(0xffffffffu, v, 2);
    v |= __shfl_xor_sync(0xffffffffu, v, 1);
    if (threadIdx.x == 0) g_is64 = (v == 0u) ? 1 : 0;
}

__device__ __forceinline__ void load_edge(const void* ei, int w, int E, int n,
                                          int& s, int& d) {
    if (w < E) {
        if (g_is64) {
            const long long* e = (const long long*)ei;
            s = (int)e[w]; d = (int)e[E + w];
        } else {
            const int* e = (const int*)ei;
            s = e[w]; d = e[E + w];
        }
        s = min(max(s, 0), n - 1);
        d = min(max(d, 0), n - 1);
    } else {
        s = d = w - E;  // self-loop
    }
}

__global__ void k_zero(int n) {
    int i = blockIdx.x * blockDim.x + threadIdx.x;
    const float4 z = make_float4(0.f, 0.f, 0.f, 0.f);
    int nAgg = n * 32;
    if (i < nAgg) {
        reinterpret_cast<float4*>(g_agg)[i] = z;
    } else if (i < nAgg + n * 2) {
        reinterpret_cast<float4*>(g_denom)[i - nAgg] = z;
    }
}

// ---------------------------------------------------------------------------
// Prep: W^T (=Bt[n][k]) in fp16, XOR-swizzled [128][128] tiles (hi only).
// ---------------------------------------------------------------------------
__global__ void k_prep(const float* __restrict__ Wl, const float* __restrict__ Wr,
                       const float* __restrict__ Ws) {
    int i = blockIdx.x * blockDim.x + threadIdx.x;
    if (i >= 3 * 16384) return;
    int m = i >> 14, kk = (i >> 7) & 127, nn = i & 127;
    const float* W = (m == 0) ? Wl : ((m == 1) ? Wr : Ws);
    g_Bh16[m * 16384 + swz(nn, kk)] = __float2half(W[kk * 128 + nn]);
}

// ---------------------------------------------------------------------------
// Mixed-precision tensor-core GEMM (mma.sync fp16):
//   which 0/1 (xl, xr):  Ah*Bh              (fp16 A, fp16 B)
//   which 2   (skip)  :  (Ah + Al)*Bh       (exact A split, fp16 B)
// Block: 64 rows x 128 cols, 256 threads (8 warps = 4m x 2n), A staged once.
// smem 64KB, regs capped -> 3 blocks/SM (24 warps) for latency coverage.
// B fragments transient (LDSM -> 2 MMA immediately) to fit the reg cap.
// ---------------------------------------------------------------------------
#define SM_AH 0
#define SM_AL 16384
#define SM_BH 32768
#define SM_TOTAL 65536

__global__ void __launch_bounds__(256, 3)
k_gemm_mma(const float* __restrict__ x, const float* __restrict__ tf,
           const float* __restrict__ bs, int n) {
    extern __shared__ char smem[];
    const uint32_t sbase = smem_u32(smem);
    const int tid = threadIdx.x;
    const int row0 = blockIdx.x * 64;

    // Stage A rows (fp32 coalesced) -> fp16 hi/lo, swizzled
    {
        __half* sh = reinterpret_cast<__half*>(smem + SM_AH);
        __half* sl = reinterpret_cast<__half*>(smem + SM_AL);
        for (int i = tid; i < 64 * 128; i += 256) {
            int r = i >> 7, k = i & 127;
            int g = row0 + r;
            float v = 0.f;
            if (g < n) v = (k < 126) ? x[g * 126 + k] : tf[g * 2 + (k - 126)];
            __half h = __float2half(v);
            int idx = swz(r, k);
            sh[idx] = h;
            sl[idx] = __float2half(v - __half2float(h));
        }
    }

    const int wid = tid >> 5;
    const int lane = tid & 31;
    const int wm = wid >> 1;
    const int wn = wid & 1;
    const int r0 = wm * 16;
    const int c0 = wn * 64;
    const int sub = lane >> 3;
    const int rin = lane & 7;

    for (int which = 0; which < 3; which++) {
        // Copy swizzled Bt image (L2-hot) into smem — byte copy
        {
            const uint4* gh = reinterpret_cast<const uint4*>(&g_Bh16[which * 16384]);
            uint4* sh = reinterpret_cast<uint4*>(smem + SM_BH);
            for (int i = tid; i < 2048; i += 256) sh[i] = gh[i];
        }
        __syncthreads();

        float acc[8][4];
#pragma unroll
        for (int nt = 0; nt < 8; nt++)
#pragma unroll
            for (int q = 0; q < 4; q++) acc[nt][q] = 0.f;

        const bool full = (which == 2);
#pragma unroll
        for (int ks = 0; ks < 8; ks++) {
            uint32_t ah[4], al[4];
            {
                const int ar = r0 + (sub & 1) * 8 + rin;
                const int ac = ks * 2 + (sub >> 1);
                const uint32_t off =
                    (uint32_t)(ar * 256 + (((ac & 8) | ((ac ^ ar) & 7)) << 4));
                LDSM_X4(ah[0], ah[1], ah[2], ah[3], sbase + SM_AH + off);
                if (full) LDSM_X4(al[0], al[1], al[2], al[3], sbase + SM_AL + off);
            }
#pragma unroll
            for (int nt2 = 0; nt2 < 4; nt2++) {
                const int br = c0 + nt2 * 16 + (sub >> 1) * 8 + rin;
                const int bc = ks * 2 + (sub & 1);
                const uint32_t off =
                    (uint32_t)(br * 256 + (((bc & 8) | ((bc ^ br) & 7)) << 4));
                uint32_t q0, q1, q2, q3;
                LDSM_X4(q0, q1, q2, q3, sbase + SM_BH + off);
                MMA_F16(acc[nt2 * 2],     ah, q0, q1);
                MMA_F16(acc[nt2 * 2 + 1], ah, q2, q3);
                if (full) {
                    MMA_F16(acc[nt2 * 2],     al, q0, q1);
                    MMA_F16(acc[nt2 * 2 + 1], al, q2, q3);
                }
            }
        }

        // Epilogue: lane l -> rows r0+(l>>2)(+8), cols c0+nt*8+(l&3)*2
#pragma unroll
        for (int nt = 0; nt < 8; nt++) {
            const int col = c0 + nt * 8 + (lane & 3) * 2;   // even
            const int ra = row0 + r0 + (lane >> 2);
            const int rb = ra + 8;
            if (full) {
                const float b0 = bs[col], b1 = bs[col + 1];
                if (ra < n) {
                    float2 v = make_float2(acc[nt][0] + b0, acc[nt][1] + b1);
                    *reinterpret_cast<float2*>(&g_skip[ra * 128 + col]) = v;
                }
                if (rb < n) {
                    float2 v = make_float2(acc[nt][2] + b0, acc[nt][3] + b1);
                    *reinterpret_cast<float2*>(&g_skip[rb * 128 + col]) = v;
                }
            } else {
                __half2* out_h = (which == 0) ? g_xl : g_xr;
                if (ra < n)
                    out_h[ra * 64 + (col >> 1)] = __floats2half2_rn(acc[nt][0], acc[nt][1]);
                if (rb < n)
                    out_h[rb * 64 + (col >> 1)] = __floats2half2_rn(acc[nt][2], acc[nt][3]);
            }
        }
        __syncthreads();
    }
}

// ---------------------------------------------------------------------------
// Fused edge pass, one edge per HALF-warp; fp16 xl/xr (one uint4 per matrix):
//   e[h] = att . lrelu(xl[s]+xr[d]); ee = exp(e);
//   denom[d][h] += ee;   agg[d] += ee * xl[s]  (fp32; normalize in k_final).
// ---------------------------------------------------------------------------
__global__ void k_edge(const void* __restrict__ ei,
                       const float* __restrict__ att, int E, int n) {
    const int gt = blockIdx.x * blockDim.x + threadIdx.x;
    const int w = gt >> 4;
    const int hl = threadIdx.x & 15;
    if (w >= E + n) return;

    int s, d;
    load_edge(ei, w, E, n, s, d);

    const uint4 aU = *reinterpret_cast<const uint4*>(&g_xl[s * 64 + hl * 4]);
    const uint4 bU = *reinterpret_cast<const uint4*>(&g_xr[d * 64 + hl * 4]);
    const float4 t0 = *reinterpret_cast<const float4*>(&att[hl * 8]);
    const float4 t1 = *reinterpret_cast<const float4*>(&att[hl * 8 + 4]);

    const __half2* ah = reinterpret_cast<const __half2*>(&aU);
    const __half2* bh = reinterpret_cast<const __half2*>(&bU);
    const float2 a01 = __half22float2(ah[0]);
    const float2 a23 = __half22float2(ah[1]);
    const float2 a45 = __half22float2(ah[2]);
    const float2 a67 = __half22float2(ah[3]);
    const float2 b01 = __half22float2(bh[0]);
    const float2 b23 = __half22float2(bh[1]);
    const float2 b45 = __half22float2(bh[2]);
    const float2 b67 = __half22float2(bh[3]);

    float m, p = 0.f;
    m = a01.x + b01.x; p += (m > 0.f ? m : 0.2f * m) * t0.x;
    m = a01.y + b01.y; p += (m > 0.f ? m : 0.2f * m) * t0.y;
    m = a23.x + b23.x; p += (m > 0.f ? m : 0.2f * m) * t0.z;
    m = a23.y + b23.y; p += (m > 0.f ? m : 0.2f * m) * t0.w;
    m = a45.x + b45.x; p += (m > 0.f ? m : 0.2f * m) * t1.x;
    m = a45.y + b45.y; p += (m > 0.f ? m : 0.2f * m) * t1.y;
    m = a67.x + b67.x; p += (m > 0.f ? m : 0.2f * m) * t1.z;
    m = a67.y + b67.y; p += (m > 0.f ? m : 0.2f * m) * t1.w;

    // head h = hl>>1 spans lanes {2h, 2h+1}
    p += __shfl_xor_sync(0xffffffffu, p, 1);

    const float ex = __expf(p);   // softmax-max dropped: |e| bounded

    if ((hl & 1) == 0) {
        atomicAdd(&g_denom[d * 8 + (hl >> 1)], ex);
    }

    float* p0 = &g_agg[d * 128 + hl * 8];
    asm volatile("red.global.add.v4.f32 [%0], {%1, %2, %3, %4};"
                 :: "l"(p0), "f"(ex * a01.x), "f"(ex * a01.y),
                    "f"(ex * a23.x), "f"(ex * a23.y) : "memory");
    asm volatile("red.global.add.v4.f32 [%0], {%1, %2, %3, %4};"
                 :: "l"(p0 + 4), "f"(ex * a45.x), "f"(ex * a45.y),
                    "f"(ex * a67.x), "f"(ex * a67.y) : "memory");
}

// ---------------------------------------------------------------------------
// Final: out = sigmoid( elu(agg/denom + bias_gat + skip) @ Wo + bo )
// ---------------------------------------------------------------------------
__global__ void k_final(const float* __restrict__ bias_gat,
                        const float* __restrict__ Wo,
                        const float* __restrict__ bo,
                        float* __restrict__ out, int n) {
    const int w = (blockIdx.x * blockDim.x + threadIdx.x) >> 5;
    const int lane = threadIdx.x & 31;
    if (w >= n) return;

    const int base = w * 128 + lane * 4;
    const float4 g  = *reinterpret_cast<const float4*>(&g_agg[base]);
    const float4 s  = *reinterpret_cast<const float4*>(&g_skip[base]);
    const float4 bg = *reinterpret_cast<const float4*>(&bias_gat[lane * 4]);
    const float4 ww = *reinterpret_cast<const float4*>(&Wo[lane * 4]);

    const float dn = 1.f / (g_denom[w * 8 + (lane >> 2)] + 1e-16f);

    float c, p = 0.f;
    c = g.x * dn + s.x + bg.x; c = (c > 0.f) ? c : expm1f(c); p += c * ww.x;
    c = g.y * dn + s.y + bg.y; c = (c > 0.f) ? c : expm1f(c); p += c * ww.y;
    c = g.z * dn + s.z + bg.z; c = (c > 0.f) ? c : expm1f(c); p += c * ww.z;
    c = g.w * dn + s.w + bg.w; c = (c > 0.f) ? c : expm1f(c); p += c * ww.w;

    p += __shfl_xor_sync(0xffffffffu, p, 16);
    p += __shfl_xor_sync(0xffffffffu, p, 8);
    p += __shfl_xor_sync(0xffffffffu, p, 4);
    p += __shfl_xor_sync(0xffffffffu, p, 2);
    p += __shfl_xor_sync(0xffffffffu, p, 1);

    if (lane == 0) {
        out[w] = 1.f / (1.f + expf(-(p + bo[0])));
    }
}

// ---------------------------------------------------------------------------
extern "C" void kernel_launch(void* const* d_in, const int* in_sizes, int n_in,
                              void* d_out, int out_size) {
    const float* x   = (const float*)d_in[0];   // [N,126]
    const float* tf  = (const float*)d_in[1];   // [N,2]
    const void*  ei  = d_in[2];                 // [2,E] int32 or int64
    const float* Wl  = (const float*)d_in[3];   // [128,128]
    const float* Wr  = (const float*)d_in[4];
    const float* att = (const float*)d_in[5];   // [8,16]
    const float* bg  = (const float*)d_in[6];   // [128]
    const float* Ws  = (const float*)d_in[7];
    const float* bs  = (const float*)d_in[8];
    const float* Wo  = (const float*)d_in[9];   // [128,1]
    const float* bo  = (const float*)d_in[10];  // [1]
    float* out = (float*)d_out;

    const int n = in_sizes[0] / 126;
    const int E = in_sizes[2] / 2;
    const int tot = E + n;

    cudaFuncSetAttribute(k_gemm_mma, cudaFuncAttributeMaxDynamicSharedMemorySize,
                         SM_TOTAL);

    k_detect<<<1, 32>>>((const unsigned int*)ei);
    k_zero<<<(n * 34 + 255) / 256, 256>>>(n);
    k_prep<<<(3 * 16384 + 255) / 256, 256>>>(Wl, Wr, Ws);

    k_gemm_mma<<<(n + 63) / 64, 256, SM_TOTAL>>>(x, tf, bs, n);

    k_edge<<<(tot + 15) / 16, 256>>>(ei, att, E, n);
    k_final<<<(n + 7) / 8, 256>>>(bg, Wo, bo, out, n);
}

// round 14
// speedup vs baseline: 1.7236x; 1.0413x over previous
#include <cuda_runtime.h>
#include <cuda_fp16.h>
#include <cstdint>

// Problem constants (shapes are fixed by the dataset)
#define MAX_N 100000
#define MAX_E 1000000

// Scratch: __device__ globals (no runtime allocation allowed)
__device__ __half2 g_xl[MAX_N * 64];     // raw @ Wl   (fp16, 2/word)
__device__ __half2 g_xr[MAX_N * 64];     // raw @ Wr   (fp16)
__device__ float   g_skip[MAX_N * 128];  // raw @ Ws + bs  (fp32)
__device__ float   g_agg[MAX_N * 128];   // segment_sum(ee * xl[src]), fp32 (real edges)
__device__ float   g_denom[MAX_N * 8];   // softmax denominators (real edges)
__device__ int     g_is64;               // edge_index dtype flag (1 = int64)
// W^T fp16 (hi only), XOR-swizzled [n][128] layout, 3 matrices
__device__ __half g_Bh16[3 * 128 * 128];

// ===================== PTX helpers (base ISA only) =========================
__device__ __forceinline__ uint32_t smem_u32(const void* p) {
    uint32_t a;
    asm("{ .reg .u64 t; cvta.to.shared.u64 t, %1; cvt.u32.u64 %0, t; }"
        : "=r"(a) : "l"(p));
    return a;
}
#define LDSM_X4(r0, r1, r2, r3, addr) \
    asm volatile("ldmatrix.sync.aligned.m8n8.x4.shared.b16 {%0,%1,%2,%3}, [%4];" \
                 : "=r"(r0), "=r"(r1), "=r"(r2), "=r"(r3) : "r"(addr))
#define MMA_F16(d, a, b0v, b1v) \
    asm volatile("mma.sync.aligned.m16n8k16.row.col.f32.f16.f16.f32 " \
                 "{%0,%1,%2,%3}, {%4,%5,%6,%7}, {%8,%9}, {%0,%1,%2,%3};" \
                 : "+f"((d)[0]), "+f"((d)[1]), "+f"((d)[2]), "+f"((d)[3]) \
                 : "r"((a)[0]), "r"((a)[1]), "r"((a)[2]), "r"((a)[3]), \
                   "r"(b0v), "r"(b1v))

// Bijective XOR swizzle within [rows][128] half tile (row stride 256B):
// chunk 0..15 -> (chunk&8) | ((chunk^r)&7); ldmatrix conflict-free.
__device__ __forceinline__ int swz(int r, int k) {
    int c = k >> 3;
    int sc = (c & 8) | ((c ^ r) & 7);
    return r * 128 + sc * 8 + (k & 7);
}

// ======================= misc small kernels ================================
__global__ void k_detect(const unsigned int* __restrict__ p) {
    unsigned int v = 0;
    for (int i = threadIdx.x; i < 128; i += 32) v |= p[2 * i + 1];
    v |= __shfl_xor_sync(0xffffffffu, v, 16);
    v |= __shfl_xor_sync(0xffffffffu, v, 8);
    v |= __shfl_xor_sync(0xffffffffu, v, 4);
    v |= __shfl_xor_sync(0xffffffffu, v, 2);
    v |= __shfl_xor_sync(0xffffffffu, v, 1);
    if (threadIdx.x == 0) g_is64 = (v == 0u) ? 1 : 0;
}

__device__ __forceinline__ int fetch_idx(const void* ei, long long pos, int n) {
    int v;
    if (g_is64) v = (int)((const long long*)ei)[pos];
    else        v = ((const int*)ei)[pos];
    return min(max(v, 0), n - 1);
}

__global__ void k_zero(int n) {
    int i = blockIdx.x * blockDim.x + threadIdx.x;
    const float4 z = make_float4(0.f, 0.f, 0.f, 0.f);
    int nAgg = n * 32;
    if (i < nAgg) {
        reinterpret_cast<float4*>(g_agg)[i] = z;
    } else if (i < nAgg + n * 2) {
        reinterpret_cast<float4*>(g_denom)[i - nAgg] = z;
    }
}

// ---------------------------------------------------------------------------
// Prep: W^T (=Bt[n][k]) in fp16, XOR-swizzled [128][128] tiles (hi only).
// ---------------------------------------------------------------------------
__global__ void k_prep(const float* __restrict__ Wl, const float* __restrict__ Wr,
                       const float* __restrict__ Ws) {
    int i = blockIdx.x * blockDim.x + threadIdx.x;
    if (i >= 3 * 16384) return;
    int m = i >> 14, kk = (i >> 7) & 127, nn = i & 127;
    const float* W = (m == 0) ? Wl : ((m == 1) ? Wr : Ws);
    g_Bh16[m * 16384 + swz(nn, kk)] = __float2half(W[kk * 128 + nn]);
}

// ---------------------------------------------------------------------------
// Mixed-precision tensor-core GEMM (unchanged from R13 — 105us, no spills):
//   which 0/1 (xl, xr):  Ah*Bh;   which 2 (skip): (Ah + Al)*Bh
// ---------------------------------------------------------------------------
#define SM_AH 0
#define SM_AL 16384
#define SM_BH 32768
#define SM_TOTAL 65536

__global__ void __launch_bounds__(256, 3)
k_gemm_mma(const float* __restrict__ x, const float* __restrict__ tf,
           const float* __restrict__ bs, int n) {
    extern __shared__ char smem[];
    const uint32_t sbase = smem_u32(smem);
    const int tid = threadIdx.x;
    const int row0 = blockIdx.x * 64;

    {
        __half* sh = reinterpret_cast<__half*>(smem + SM_AH);
        __half* sl = reinterpret_cast<__half*>(smem + SM_AL);
        for (int i = tid; i < 64 * 128; i += 256) {
            int r = i >> 7, k = i & 127;
            int g = row0 + r;
            float v = 0.f;
            if (g < n) v = (k < 126) ? x[g * 126 + k] : tf[g * 2 + (k - 126)];
            __half h = __float2half(v);
            int idx = swz(r, k);
            sh[idx] = h;
            sl[idx] = __float2half(v - __half2float(h));
        }
    }

    const int wid = tid >> 5;
    const int lane = tid & 31;
    const int wm = wid >> 1;
    const int wn = wid & 1;
    const int r0 = wm * 16;
    const int c0 = wn * 64;
    const int sub = lane >> 3;
    const int rin = lane & 7;

    for (int which = 0; which < 3; which++) {
        {
            const uint4* gh = reinterpret_cast<const uint4*>(&g_Bh16[which * 16384]);
            uint4* sh = reinterpret_cast<uint4*>(smem + SM_BH);
            for (int i = tid; i < 2048; i += 256) sh[i] = gh[i];
        }
        __syncthreads();

        float acc[8][4];
#pragma unroll
        for (int nt = 0; nt < 8; nt++)
#pragma unroll
            for (int q = 0; q < 4; q++) acc[nt][q] = 0.f;

        const bool full = (which == 2);
#pragma unroll
        for (int ks = 0; ks < 8; ks++) {
            uint32_t ah[4], al[4];
            {
                const int ar = r0 + (sub & 1) * 8 + rin;
                const int ac = ks * 2 + (sub >> 1);
                const uint32_t off =
                    (uint32_t)(ar * 256 + (((ac & 8) | ((ac ^ ar) & 7)) << 4));
                LDSM_X4(ah[0], ah[1], ah[2], ah[3], sbase + SM_AH + off);
                if (full) LDSM_X4(al[0], al[1], al[2], al[3], sbase + SM_AL + off);
            }
#pragma unroll
            for (int nt2 = 0; nt2 < 4; nt2++) {
                const int br = c0 + nt2 * 16 + (sub >> 1) * 8 + rin;
                const int bc = ks * 2 + (sub & 1);
                const uint32_t off =
                    (uint32_t)(br * 256 + (((bc & 8) | ((bc ^ br) & 7)) << 4));
                uint32_t q0, q1, q2, q3;
                LDSM_X4(q0, q1, q2, q3, sbase + SM_BH + off);
                MMA_F16(acc[nt2 * 2],     ah, q0, q1);
                MMA_F16(acc[nt2 * 2 + 1], ah, q2, q3);
                if (full) {
                    MMA_F16(acc[nt2 * 2],     al, q0, q1);
                    MMA_F16(acc[nt2 * 2 + 1], al, q2, q3);
                }
            }
        }

#pragma unroll
        for (int nt = 0; nt < 8; nt++) {
            const int col = c0 + nt * 8 + (lane & 3) * 2;
            const int ra = row0 + r0 + (lane >> 2);
            const int rb = ra + 8;
            if (full) {
                const float b0 = bs[col], b1 = bs[col + 1];
                if (ra < n) {
                    float2 v = make_float2(acc[nt][0] + b0, acc[nt][1] + b1);
                    *reinterpret_cast<float2*>(&g_skip[ra * 128 + col]) = v;
                }
                if (rb < n) {
                    float2 v = make_float2(acc[nt][2] + b0, acc[nt][3] + b1);
                    *reinterpret_cast<float2*>(&g_skip[rb * 128 + col]) = v;
                }
            } else {
                __half2* out_h = (which == 0) ? g_xl : g_xr;
                if (ra < n)
                    out_h[ra * 64 + (col >> 1)] = __floats2half2_rn(acc[nt][0], acc[nt][1]);
                if (rb < n)
                    out_h[rb * 64 + (col >> 1)] = __floats2half2_rn(acc[nt][2], acc[nt][3]);
            }
        }
        __syncthreads();
    }
}

// ---------------------------------------------------------------------------
// Edge score + reduction for one edge (helper; exact same math as before)
// ---------------------------------------------------------------------------
__device__ __forceinline__ void edge_work(const uint4& aU, const uint4& bU,
                                          const float4& t0, const float4& t1,
                                          int hl, int d) {
    const __half2* ah = reinterpret_cast<const __half2*>(&aU);
    const __half2* bh = reinterpret_cast<const __half2*>(&bU);
    const float2 a01 = __half22float2(ah[0]);
    const float2 a23 = __half22float2(ah[1]);
    const float2 a45 = __half22float2(ah[2]);
    const float2 a67 = __half22float2(ah[3]);
    const float2 b01 = __half22float2(bh[0]);
    const float2 b23 = __half22float2(bh[1]);
    const float2 b45 = __half22float2(bh[2]);
    const float2 b67 = __half22float2(bh[3]);

    float m, p = 0.f;
    m = a01.x + b01.x; p += (m > 0.f ? m : 0.2f * m) * t0.x;
    m = a01.y + b01.y; p += (m > 0.f ? m : 0.2f * m) * t0.y;
    m = a23.x + b23.x; p += (m > 0.f ? m : 0.2f * m) * t0.z;
    m = a23.y + b23.y; p += (m > 0.f ? m : 0.2f * m) * t0.w;
    m = a45.x + b45.x; p += (m > 0.f ? m : 0.2f * m) * t1.x;
    m = a45.y + b45.y; p += (m > 0.f ? m : 0.2f * m) * t1.y;
    m = a67.x + b67.x; p += (m > 0.f ? m : 0.2f * m) * t1.z;
    m = a67.y + b67.y; p += (m > 0.f ? m : 0.2f * m) * t1.w;

    // head h = hl>>1 spans lanes {2h, 2h+1}
    p += __shfl_xor_sync(0xffffffffu, p, 1);

    const float ex = __expf(p);   // softmax-max dropped: |e| bounded

    if ((hl & 1) == 0) {
        atomicAdd(&g_denom[d * 8 + (hl >> 1)], ex);
    }

    float* p0 = &g_agg[d * 128 + hl * 8];
    asm volatile("red.global.add.v4.f32 [%0], {%1, %2, %3, %4};"
                 :: "l"(p0), "f"(ex * a01.x), "f"(ex * a01.y),
                    "f"(ex * a23.x), "f"(ex * a23.y) : "memory");
    asm volatile("red.global.add.v4.f32 [%0], {%1, %2, %3, %4};"
                 :: "l"(p0 + 4), "f"(ex * a45.x), "f"(ex * a45.y),
                    "f"(ex * a67.x), "f"(ex * a67.y) : "memory");
}

// ---------------------------------------------------------------------------
// Fused edge pass: TWO edges per half-warp (4 gathers in flight -> MLP x2).
// Real edges only; self-loops handled in k_final.
// ---------------------------------------------------------------------------
__global__ void k_edge(const void* __restrict__ ei,
                       const float* __restrict__ att, int E, int n) {
    const int gt = blockIdx.x * blockDim.x + threadIdx.x;
    const int pair = gt >> 4;
    const int hl = threadIdx.x & 15;
    const int w0 = pair * 2;
    if (w0 >= E) return;
    const int w1 = w0 + 1;
    const bool has1 = (w1 < E);

    int s0 = fetch_idx(ei, w0, n);
    int d0 = fetch_idx(ei, (long long)E + w0, n);
    int s1 = s0, d1 = d0;
    if (has1) {
        s1 = fetch_idx(ei, w1, n);
        d1 = fetch_idx(ei, (long long)E + w1, n);
    }

    // All four gathers issued back-to-back (MLP = 4 per lane)
    const uint4 a0 = *reinterpret_cast<const uint4*>(&g_xl[s0 * 64 + hl * 4]);
    const uint4 b0 = *reinterpret_cast<const uint4*>(&g_xr[d0 * 64 + hl * 4]);
    const uint4 a1 = *reinterpret_cast<const uint4*>(&g_xl[s1 * 64 + hl * 4]);
    const uint4 b1 = *reinterpret_cast<const uint4*>(&g_xr[d1 * 64 + hl * 4]);

    const float4 t0 = *reinterpret_cast<const float4*>(&att[hl * 8]);
    const float4 t1 = *reinterpret_cast<const float4*>(&att[hl * 8 + 4]);

    edge_work(a0, b0, t0, t1, hl, d0);
    if (has1) edge_work(a1, b1, t0, t1, hl, d1);
}

// ---------------------------------------------------------------------------
// Final: add self-loop contribution, then
//   out = sigmoid( elu((agg+ee*xl)/(denom+ee) + bias_gat + skip) @ Wo + bo )
// One warp per node; lane covers cols lane*4..+3 (head = lane>>2).
// ---------------------------------------------------------------------------
__global__ void k_final(const float* __restrict__ att,
                        const float* __restrict__ bias_gat,
                        const float* __restrict__ Wo,
                        const float* __restrict__ bo,
                        float* __restrict__ out, int n) {
    const int w = (blockIdx.x * blockDim.x + threadIdx.x) >> 5;
    const int lane = threadIdx.x & 31;
    if (w >= n) return;

    // Self-loop: xl[w], xr[w] (fp16 rows, coalesced)
    const uint2 xlU = *reinterpret_cast<const uint2*>(&g_xl[w * 64 + lane * 2]);
    const uint2 xrU = *reinterpret_cast<const uint2*>(&g_xr[w * 64 + lane * 2]);
    const __half2* xlh = reinterpret_cast<const __half2*>(&xlU);
    const __half2* xrh = reinterpret_cast<const __half2*>(&xrU);
    const float2 xl01 = __half22float2(xlh[0]);
    const float2 xl23 = __half22float2(xlh[1]);
    const float2 xr01 = __half22float2(xrh[0]);
    const float2 xr23 = __half22float2(xrh[1]);
    const float4 at4 = *reinterpret_cast<const float4*>(&att[lane * 4]);

    float m, p2 = 0.f;
    m = xl01.x + xr01.x; p2 += (m > 0.f ? m : 0.2f * m) * at4.x;
    m = xl01.y + xr01.y; p2 += (m > 0.f ? m : 0.2f * m) * at4.y;
    m = xl23.x + xr23.x; p2 += (m > 0.f ? m : 0.2f * m) * at4.z;
    m = xl23.y + xr23.y; p2 += (m > 0.f ? m : 0.2f * m) * at4.w;
    // sum over the head's 16 channels (4-lane group)
    p2 += __shfl_xor_sync(0xffffffffu, p2, 1);
    p2 += __shfl_xor_sync(0xffffffffu, p2, 2);
    const float ee = __expf(p2);

    const int base = w * 128 + lane * 4;
    const float4 g  = *reinterpret_cast<const float4*>(&g_agg[base]);
    const float4 s  = *reinterpret_cast<const float4*>(&g_skip[base]);
    const float4 bg = *reinterpret_cast<const float4*>(&bias_gat[lane * 4]);
    const float4 ww = *reinterpret_cast<const float4*>(&Wo[lane * 4]);

    const float dn = 1.f / (g_denom[w * 8 + (lane >> 2)] + ee + 1e-16f);

    float c, p = 0.f;
    c = (g.x + ee * xl01.x) * dn + s.x + bg.x; c = (c > 0.f) ? c : expm1f(c); p += c * ww.x;
    c = (g.y + ee * xl01.y) * dn + s.y + bg.y; c = (c > 0.f) ? c : expm1f(c); p += c * ww.y;
    c = (g.z + ee * xl23.x) * dn + s.z + bg.z; c = (c > 0.f) ? c : expm1f(c); p += c * ww.z;
    c = (g.w + ee * xl23.y) * dn + s.w + bg.w; c = (c > 0.f) ? c : expm1f(c); p += c * ww.w;

    p += __shfl_xor_sync(0xffffffffu, p, 16);
    p += __shfl_xor_sync(0xffffffffu, p, 8);
    p += __shfl_xor_sync(0xffffffffu, p, 4);
    p += __shfl_xor_sync(0xffffffffu, p, 2);
    p += __shfl_xor_sync(0xffffffffu, p, 1);

    if (lane == 0) {
        out[w] = 1.f / (1.f + expf(-(p + bo[0])));
    }
}

// ---------------------------------------------------------------------------
extern "C" void kernel_launch(void* const* d_in, const int* in_sizes, int n_in,
                              void* d_out, int out_size) {
    const float* x   = (const float*)d_in[0];   // [N,126]
    const float* tf  = (const float*)d_in[1];   // [N,2]
    const void*  ei  = d_in[2];                 // [2,E] int32 or int64
    const float* Wl  = (const float*)d_in[3];   // [128,128]
    const float* Wr  = (const float*)d_in[4];
    const float* att = (const float*)d_in[5];   // [8,16]
    const float* bg  = (const float*)d_in[6];   // [128]
    const float* Ws  = (const float*)d_in[7];
    const float* bs  = (const float*)d_in[8];
    const float* Wo  = (const float*)d_in[9];   // [128,1]
    const float* bo  = (const float*)d_in[10];  // [1]
    float* out = (float*)d_out;

    const int n = in_sizes[0] / 126;
    const int E = in_sizes[2] / 2;
    const int pairs = (E + 1) / 2;

    cudaFuncSetAttribute(k_gemm_mma, cudaFuncAttributeMaxDynamicSharedMemorySize,
                         SM_TOTAL);

    k_detect<<<1, 32>>>((const unsigned int*)ei);
    k_zero<<<(n * 34 + 255) / 256, 256>>>(n);
    k_prep<<<(3 * 16384 + 255) / 256, 256>>>(Wl, Wr, Ws);

    k_gemm_mma<<<(n + 63) / 64, 256, SM_TOTAL>>>(x, tf, bs, n);

    k_edge<<<(pairs + 15) / 16, 256>>>(ei, att, E, n);
    k_final<<<(n + 7) / 8, 256>>>(att, bg, Wo, bo, out, n);
}

// round 15
// speedup vs baseline: 1.7817x; 1.0337x over previous
#include <cuda_runtime.h>
#include <cuda_fp16.h>
#include <cstdint>

// Problem constants (shapes are fixed by the dataset)
#define MAX_N 100000
#define MAX_E 1000000

// Scratch: __device__ globals (no runtime allocation allowed)
__device__ __half2 g_xl[MAX_N * 64];     // raw @ Wl   (fp16, 2/word)
__device__ __half2 g_xr[MAX_N * 64];     // raw @ Wr   (fp16)
__device__ float   g_skip[MAX_N * 128];  // raw @ Ws + bs  (fp32)
__device__ float   g_agg[MAX_N * 128];   // segment_sum(ee * xl[src]), fp32 (real edges)
__device__ float   g_denom[MAX_N * 8];   // softmax denominators (real edges)
__device__ int     g_is64;               // edge_index dtype flag (1 = int64)
// W^T fp16 (hi only), XOR-swizzled [n][128] layout, 3 matrices
__device__ __half g_Bh16[3 * 128 * 128];

// ===================== PTX helpers (base ISA only) =========================
__device__ __forceinline__ uint32_t smem_u32(const void* p) {
    uint32_t a;
    asm("{ .reg .u64 t; cvta.to.shared.u64 t, %1; cvt.u32.u64 %0, t; }"
        : "=r"(a) : "l"(p));
    return a;
}
#define LDSM_X4(r0, r1, r2, r3, addr) \
    asm volatile("ldmatrix.sync.aligned.m8n8.x4.shared.b16 {%0,%1,%2,%3}, [%4];" \
                 : "=r"(r0), "=r"(r1), "=r"(r2), "=r"(r3) : "r"(addr))
#define MMA_F16(d, a, b0v, b1v) \
    asm volatile("mma.sync.aligned.m16n8k16.row.col.f32.f16.f16.f32 " \
                 "{%0,%1,%2,%3}, {%4,%5,%6,%7}, {%8,%9}, {%0,%1,%2,%3};" \
                 : "+f"((d)[0]), "+f"((d)[1]), "+f"((d)[2]), "+f"((d)[3]) \
                 : "r"((a)[0]), "r"((a)[1]), "r"((a)[2]), "r"((a)[3]), \
                   "r"(b0v), "r"(b1v))
#define CP_ASYNC16(saddr, gptr) \
    asm volatile("cp.async.cg.shared.global [%0], [%1], 16;" \
                 :: "r"(saddr), "l"(gptr) : "memory")
#define CP_COMMIT() asm volatile("cp.async.commit_group;" ::: "memory")
#define CP_WAIT0()  asm volatile("cp.async.wait_group 0;" ::: "memory")

// Bijective XOR swizzle within [rows][128] half tile (row stride 256B):
// chunk 0..15 -> (chunk&8) | ((chunk^r)&7); ldmatrix conflict-free.
__device__ __forceinline__ int swz(int r, int k) {
    int c = k >> 3;
    int sc = (c & 8) | ((c ^ r) & 7);
    return r * 128 + sc * 8 + (k & 7);
}

__device__ __forceinline__ int fetch_idx(const void* ei, long long pos, int n) {
    int v;
    if (g_is64) v = (int)((const long long*)ei)[pos];
    else        v = ((const int*)ei)[pos];
    return min(max(v, 0), n - 1);
}

// ---------------------------------------------------------------------------
// Fused init: zero agg/denom + build fp16 W^T tiles + dtype detect.
// Zero range: [0, n*34) float4s.  Prep range: next 49152 ids.
// Detect: last block, first warp.
// ---------------------------------------------------------------------------
__global__ void k_init(const float* __restrict__ Wl, const float* __restrict__ Wr,
                       const float* __restrict__ Ws,
                       const unsigned int* __restrict__ eiw, int n) {
    if (blockIdx.x == gridDim.x - 1) {           // detect block
        if (threadIdx.x < 32) {
            unsigned int v = 0;
            for (int i = threadIdx.x; i < 128; i += 32) v |= eiw[2 * i + 1];
            v |= __shfl_xor_sync(0xffffffffu, v, 16);
            v |= __shfl_xor_sync(0xffffffffu, v, 8);
            v |= __shfl_xor_sync(0xffffffffu, v, 4);
            v |= __shfl_xor_sync(0xffffffffu, v, 2);
            v |= __shfl_xor_sync(0xffffffffu, v, 1);
            if (threadIdx.x == 0) g_is64 = (v == 0u) ? 1 : 0;
        }
        return;
    }
    int i = blockIdx.x * blockDim.x + threadIdx.x;
    const int nZero = n * 34;                    // n*32 agg + n*2 denom (float4)
    if (i < nZero) {
        const float4 z = make_float4(0.f, 0.f, 0.f, 0.f);
        if (i < n * 32) reinterpret_cast<float4*>(g_agg)[i] = z;
        else            reinterpret_cast<float4*>(g_denom)[i - n * 32] = z;
        return;
    }
    i -= nZero;
    if (i < 3 * 16384) {
        int m = i >> 14, kk = (i >> 7) & 127, nn = i & 127;
        const float* W = (m == 0) ? Wl : ((m == 1) ? Wr : Ws);
        g_Bh16[m * 16384 + swz(nn, kk)] = __float2half(W[kk * 128 + nn]);
    }
}

// ---------------------------------------------------------------------------
// Mixed-precision tensor-core GEMM (R13 structure + cp.async B prefetch):
//   which 0/1 (xl, xr):  Ah*Bh;   which 2 (skip): (Ah + Al)*Bh
// ---------------------------------------------------------------------------
#define SM_AH 0
#define SM_AL 16384
#define SM_BH 32768
#define SM_TOTAL 65536

__global__ void __launch_bounds__(256, 3)
k_gemm_mma(const float* __restrict__ x, const float* __restrict__ tf,
           const float* __restrict__ bs, int n) {
    extern __shared__ char smem[];
    const uint32_t sbase = smem_u32(smem);
    const int tid = threadIdx.x;
    const int row0 = blockIdx.x * 64;

    // Prefetch B0 (overlaps with A staging)
    {
        const uint4* gB = reinterpret_cast<const uint4*>(g_Bh16);
        for (int i = tid; i < 2048; i += 256)
            CP_ASYNC16(sbase + SM_BH + i * 16, gB + i);
        CP_COMMIT();
    }

    // Stage A rows (fp32 coalesced) -> fp16 hi/lo, swizzled
    {
        __half* sh = reinterpret_cast<__half*>(smem + SM_AH);
        __half* sl = reinterpret_cast<__half*>(smem + SM_AL);
        for (int i = tid; i < 64 * 128; i += 256) {
            int r = i >> 7, k = i & 127;
            int g = row0 + r;
            float v = 0.f;
            if (g < n) v = (k < 126) ? x[g * 126 + k] : tf[g * 2 + (k - 126)];
            __half h = __float2half(v);
            int idx = swz(r, k);
            sh[idx] = h;
            sl[idx] = __float2half(v - __half2float(h));
        }
    }
    CP_WAIT0();
    __syncthreads();

    const int wid = tid >> 5;
    const int lane = tid & 31;
    const int wm = wid >> 1;
    const int wn = wid & 1;
    const int r0 = wm * 16;
    const int c0 = wn * 64;
    const int sub = lane >> 3;
    const int rin = lane & 7;

    for (int which = 0; which < 3; which++) {
        float acc[8][4];
#pragma unroll
        for (int nt = 0; nt < 8; nt++)
#pragma unroll
            for (int q = 0; q < 4; q++) acc[nt][q] = 0.f;

        const bool full = (which == 2);
#pragma unroll
        for (int ks = 0; ks < 8; ks++) {
            uint32_t ah[4], al[4];
            {
                const int ar = r0 + (sub & 1) * 8 + rin;
                const int ac = ks * 2 + (sub >> 1);
                const uint32_t off =
                    (uint32_t)(ar * 256 + (((ac & 8) | ((ac ^ ar) & 7)) << 4));
                LDSM_X4(ah[0], ah[1], ah[2], ah[3], sbase + SM_AH + off);
                if (full) LDSM_X4(al[0], al[1], al[2], al[3], sbase + SM_AL + off);
            }
#pragma unroll
            for (int nt2 = 0; nt2 < 4; nt2++) {
                const int br = c0 + nt2 * 16 + (sub >> 1) * 8 + rin;
                const int bc = ks * 2 + (sub & 1);
                const uint32_t off =
                    (uint32_t)(br * 256 + (((bc & 8) | ((bc ^ br) & 7)) << 4));
                uint32_t q0, q1, q2, q3;
                LDSM_X4(q0, q1, q2, q3, sbase + SM_BH + off);
                MMA_F16(acc[nt2 * 2],     ah, q0, q1);
                MMA_F16(acc[nt2 * 2 + 1], ah, q2, q3);
                if (full) {
                    MMA_F16(acc[nt2 * 2],     al, q0, q1);
                    MMA_F16(acc[nt2 * 2 + 1], al, q2, q3);
                }
            }
        }

        __syncthreads();   // all warps done reading B[which]
        if (which < 2) {   // prefetch next B, overlapped with epilogue stores
            const uint4* gB =
                reinterpret_cast<const uint4*>(&g_Bh16[(which + 1) * 16384]);
            for (int i = tid; i < 2048; i += 256)
                CP_ASYNC16(sbase + SM_BH + i * 16, gB + i);
            CP_COMMIT();
        }

        // Epilogue: lane l -> rows r0+(l>>2)(+8), cols c0+nt*8+(l&3)*2
#pragma unroll
        for (int nt = 0; nt < 8; nt++) {
            const int col = c0 + nt * 8 + (lane & 3) * 2;
            const int ra = row0 + r0 + (lane >> 2);
            const int rb = ra + 8;
            if (full) {
                const float b0 = bs[col], b1 = bs[col + 1];
                if (ra < n) {
                    float2 v = make_float2(acc[nt][0] + b0, acc[nt][1] + b1);
                    *reinterpret_cast<float2*>(&g_skip[ra * 128 + col]) = v;
                }
                if (rb < n) {
                    float2 v = make_float2(acc[nt][2] + b0, acc[nt][3] + b1);
                    *reinterpret_cast<float2*>(&g_skip[rb * 128 + col]) = v;
                }
            } else {
                __half2* out_h = (which == 0) ? g_xl : g_xr;
                if (ra < n)
                    out_h[ra * 64 + (col >> 1)] = __floats2half2_rn(acc[nt][0], acc[nt][1]);
                if (rb < n)
                    out_h[rb * 64 + (col >> 1)] = __floats2half2_rn(acc[nt][2], acc[nt][3]);
            }
        }
        if (which < 2) {
            CP_WAIT0();
            __syncthreads();
        }
    }
}

// ---------------------------------------------------------------------------
// Edge score + reduction for one edge.  Denom: the 8 per-head ee values are
// compacted to lanes (hl&7)==0 via shuffles and issued as TWO v4 vector
// reductions instead of 8 scalar atomics (same additions, 4x fewer L2 ops).
// ---------------------------------------------------------------------------
__device__ __forceinline__ void edge_work(const uint4& aU, const uint4& bU,
                                          const float4& t0, const float4& t1,
                                          int lane, int hl, int d) {
    const __half2* ah = reinterpret_cast<const __half2*>(&aU);
    const __half2* bh = reinterpret_cast<const __half2*>(&bU);
    const float2 a01 = __half22float2(ah[0]);
    const float2 a23 = __half22float2(ah[1]);
    const float2 a45 = __half22float2(ah[2]);
    const float2 a67 = __half22float2(ah[3]);
    const float2 b01 = __half22float2(bh[0]);
    const float2 b23 = __half22float2(bh[1]);
    const float2 b45 = __half22float2(bh[2]);
    const float2 b67 = __half22float2(bh[3]);

    float m, p = 0.f;
    m = a01.x + b01.x; p += (m > 0.f ? m : 0.2f * m) * t0.x;
    m = a01.y + b01.y; p += (m > 0.f ? m : 0.2f * m) * t0.y;
    m = a23.x + b23.x; p += (m > 0.f ? m : 0.2f * m) * t0.z;
    m = a23.y + b23.y; p += (m > 0.f ? m : 0.2f * m) * t0.w;
    m = a45.x + b45.x; p += (m > 0.f ? m : 0.2f * m) * t1.x;
    m = a45.y + b45.y; p += (m > 0.f ? m : 0.2f * m) * t1.y;
    m = a67.x + b67.x; p += (m > 0.f ? m : 0.2f * m) * t1.z;
    m = a67.y + b67.y; p += (m > 0.f ? m : 0.2f * m) * t1.w;

    // head h = hl>>1 spans lanes {2h, 2h+1}
    p += __shfl_xor_sync(0xffffffffu, p, 1);

    const float ex = __expf(p);   // softmax-max dropped: |e| bounded

    // Compact ee of 4 heads into lanes hl==0 and hl==8 (per half-warp)
    const int basel = lane & 24;  // 0/8 (+16 for upper half-warp)
    const float v0 = __shfl_sync(0xffffffffu, ex, basel + 0);
    const float v1 = __shfl_sync(0xffffffffu, ex, basel + 2);
    const float v2 = __shfl_sync(0xffffffffu, ex, basel + 4);
    const float v3 = __shfl_sync(0xffffffffu, ex, basel + 6);
    if ((hl & 7) == 0) {
        float* dp = &g_denom[d * 8 + (hl >> 1)];   // hl=0 -> +0, hl=8 -> +4
        asm volatile("red.global.add.v4.f32 [%0], {%1, %2, %3, %4};"
                     :: "l"(dp), "f"(v0), "f"(v1), "f"(v2), "f"(v3) : "memory");
    }

    float* p0 = &g_agg[d * 128 + hl * 8];
    asm volatile("red.global.add.v4.f32 [%0], {%1, %2, %3, %4};"
                 :: "l"(p0), "f"(ex * a01.x), "f"(ex * a01.y),
                    "f"(ex * a23.x), "f"(ex * a23.y) : "memory");
    asm volatile("red.global.add.v4.f32 [%0], {%1, %2, %3, %4};"
                 :: "l"(p0 + 4), "f"(ex * a45.x), "f"(ex * a45.y),
                    "f"(ex * a67.x), "f"(ex * a67.y) : "memory");
}

// ---------------------------------------------------------------------------
// Fused edge pass: TWO edges per half-warp (4 gathers in flight).
// Real edges only; self-loops handled in k_final.
// ---------------------------------------------------------------------------
__global__ void k_edge(const void* __restrict__ ei,
                       const float* __restrict__ att, int E, int n) {
    const int gt = blockIdx.x * blockDim.x + threadIdx.x;
    const int pair = gt >> 4;
    const int lane = threadIdx.x & 31;
    const int hl = lane & 15;
    const int w0 = pair * 2;
    if (w0 >= E) return;
    const int w1 = w0 + 1;
    const bool has1 = (w1 < E);

    int s0 = fetch_idx(ei, w0, n);
    int d0 = fetch_idx(ei, (long long)E + w0, n);
    int s1 = s0, d1 = d0;
    if (has1) {
        s1 = fetch_idx(ei, w1, n);
        d1 = fetch_idx(ei, (long long)E + w1, n);
    }

    // All four gathers issued back-to-back (MLP = 4 per lane)
    const uint4 a0 = *reinterpret_cast<const uint4*>(&g_xl[s0 * 64 + hl * 4]);
    const uint4 b0 = *reinterpret_cast<const uint4*>(&g_xr[d0 * 64 + hl * 4]);
    const uint4 a1 = *reinterpret_cast<const uint4*>(&g_xl[s1 * 64 + hl * 4]);
    const uint4 b1 = *reinterpret_cast<const uint4*>(&g_xr[d1 * 64 + hl * 4]);

    const float4 t0 = *reinterpret_cast<const float4*>(&att[hl * 8]);
    const float4 t1 = *reinterpret_cast<const float4*>(&att[hl * 8 + 4]);

    edge_work(a0, b0, t0, t1, lane, hl, d0);
    if (has1) edge_work(a1, b1, t0, t1, lane, hl, d1);
}

// ---------------------------------------------------------------------------
// Final: add self-loop contribution, then
//   out = sigmoid( elu((agg+ee*xl)/(denom+ee) + bias_gat + skip) @ Wo + bo )
// One warp per node; lane covers cols lane*4..+3 (head = lane>>2).
// ---------------------------------------------------------------------------
__global__ void k_final(const float* __restrict__ att,
                        const float* __restrict__ bias_gat,
                        const float* __restrict__ Wo,
                        const float* __restrict__ bo,
                        float* __restrict__ out, int n) {
    const int w = (blockIdx.x * blockDim.x + threadIdx.x) >> 5;
    const int lane = threadIdx.x & 31;
    if (w >= n) return;

    // Self-loop: xl[w], xr[w] (fp16 rows, coalesced)
    const uint2 xlU = *reinterpret_cast<const uint2*>(&g_xl[w * 64 + lane * 2]);
    const uint2 xrU = *reinterpret_cast<const uint2*>(&g_xr[w * 64 + lane * 2]);
    const __half2* xlh = reinterpret_cast<const __half2*>(&xlU);
    const __half2* xrh = reinterpret_cast<const __half2*>(&xrU);
    const float2 xl01 = __half22float2(xlh[0]);
    const float2 xl23 = __half22float2(xlh[1]);
    const float2 xr01 = __half22float2(xrh[0]);
    const float2 xr23 = __half22float2(xrh[1]);
    const float4 at4 = *reinterpret_cast<const float4*>(&att[lane * 4]);

    float m, p2 = 0.f;
    m = xl01.x + xr01.x; p2 += (m > 0.f ? m : 0.2f * m) * at4.x;
    m = xl01.y + xr01.y; p2 += (m > 0.f ? m : 0.2f * m) * at4.y;
    m = xl23.x + xr23.x; p2 += (m > 0.f ? m : 0.2f * m) * at4.z;
    m = xl23.y + xr23.y; p2 += (m > 0.f ? m : 0.2f * m) * at4.w;
    // sum over the head's 16 channels (4-lane group)
    p2 += __shfl_xor_sync(0xffffffffu, p2, 1);
    p2 += __shfl_xor_sync(0xffffffffu, p2, 2);
    const float ee = __expf(p2);

    const int base = w * 128 + lane * 4;
    const float4 g  = *reinterpret_cast<const float4*>(&g_agg[base]);
    const float4 s  = *reinterpret_cast<const float4*>(&g_skip[base]);
    const float4 bg = *reinterpret_cast<const float4*>(&bias_gat[lane * 4]);
    const float4 ww = *reinterpret_cast<const float4*>(&Wo[lane * 4]);

    const float dn = 1.f / (g_denom[w * 8 + (lane >> 2)] + ee + 1e-16f);

    float c, p = 0.f;
    c = (g.x + ee * xl01.x) * dn + s.x + bg.x; c = (c > 0.f) ? c : expm1f(c); p += c * ww.x;
    c = (g.y + ee * xl01.y) * dn + s.y + bg.y; c = (c > 0.f) ? c : expm1f(c); p += c * ww.y;
    c = (g.z + ee * xl23.x) * dn + s.z + bg.z; c = (c > 0.f) ? c : expm1f(c); p += c * ww.z;
    c = (g.w + ee * xl23.y) * dn + s.w + bg.w; c = (c > 0.f) ? c : expm1f(c); p += c * ww.w;

    p += __shfl_xor_sync(0xffffffffu, p, 16);
    p += __shfl_xor_sync(0xffffffffu, p, 8);
    p += __shfl_xor_sync(0xffffffffu, p, 4);
    p += __shfl_xor_sync(0xffffffffu, p, 2);
    p += __shfl_xor_sync(0xffffffffu, p, 1);

    if (lane == 0) {
        out[w] = 1.f / (1.f + expf(-(p + bo[0])));
    }
}

// ---------------------------------------------------------------------------
extern "C" void kernel_launch(void* const* d_in, const int* in_sizes, int n_in,
                              void* d_out, int out_size) {
    const float* x   = (const float*)d_in[0];   // [N,126]
    const float* tf  = (const float*)d_in[1];   // [N,2]
    const void*  ei  = d_in[2];                 // [2,E] int32 or int64
    const float* Wl  = (const float*)d_in[3];   // [128,128]
    const float* Wr  = (const float*)d_in[4];
    const float* att = (const float*)d_in[5];   // [8,16]
    const float* bg  = (const float*)d_in[6];   // [128]
    const float* Ws  = (const float*)d_in[7];
    const float* bs  = (const float*)d_in[8];
    const float* Wo  = (const float*)d_in[9];   // [128,1]
    const float* bo  = (const float*)d_in[10];  // [1]
    float* out = (float*)d_out;

    const int n = in_sizes[0] / 126;
    const int E = in_sizes[2] / 2;
    const int pairs = (E + 1) / 2;

    cudaFuncSetAttribute(k_gemm_mma, cudaFuncAttributeMaxDynamicSharedMemorySize,
                         SM_TOTAL);

    const int initWork = n * 34 + 3 * 16384;
    k_init<<<(initWork + 255) / 256 + 1, 256>>>(Wl, Wr, Ws,
                                                (const unsigned int*)ei, n);

    k_gemm_mma<<<(n + 63) / 64, 256, SM_TOTAL>>>(x, tf, bs, n);

    k_edge<<<(pairs + 15) / 16, 256>>>(ei, att, E, n);
    k_final<<<(n + 7) / 8, 256>>>(att, bg, Wo, bo, out, n);
}

// round 16
// speedup vs baseline: 2.3523x; 1.3202x over previous
#include <cuda_runtime.h>
#include <cuda_fp16.h>
#include <cstdint>

// Problem constants (shapes are fixed by the dataset)
#define MAX_N 100000
#define MAX_E 1000000

// Scratch: __device__ globals (no runtime allocation allowed)
__device__ __half2 g_xl[MAX_N * 64];     // raw @ Wl   (fp16, 2/word)
__device__ __half2 g_xr[MAX_N * 64];     // raw @ Wr   (fp16)
__device__ float   g_skip[MAX_N * 128];  // raw @ Ws + bs  (fp32)
__device__ __align__(16) __half2 g_agg[MAX_N * 64];  // sum(ee*xl[src]), fp16
__device__ float   g_denom[MAX_N * 8];   // softmax denominators (fp32)
__device__ int     g_is64;               // edge_index dtype flag (1 = int64)
// W^T fp16 (hi only), XOR-swizzled [n][128] layout, 3 matrices
__device__ __half g_Bh16[3 * 128 * 128];

// ===================== PTX helpers (base ISA only) =========================
__device__ __forceinline__ uint32_t smem_u32(const void* p) {
    uint32_t a;
    asm("{ .reg .u64 t; cvta.to.shared.u64 t, %1; cvt.u32.u64 %0, t; }"
        : "=r"(a) : "l"(p));
    return a;
}
#define LDSM_X4(r0, r1, r2, r3, addr) \
    asm volatile("ldmatrix.sync.aligned.m8n8.x4.shared.b16 {%0,%1,%2,%3}, [%4];" \
                 : "=r"(r0), "=r"(r1), "=r"(r2), "=r"(r3) : "r"(addr))
#define MMA_F16(d, a, b0v, b1v) \
    asm volatile("mma.sync.aligned.m16n8k16.row.col.f32.f16.f16.f32 " \
                 "{%0,%1,%2,%3}, {%4,%5,%6,%7}, {%8,%9}, {%0,%1,%2,%3};" \
                 : "+f"((d)[0]), "+f"((d)[1]), "+f"((d)[2]), "+f"((d)[3]) \
                 : "r"((a)[0]), "r"((a)[1]), "r"((a)[2]), "r"((a)[3]), \
                   "r"(b0v), "r"(b1v))
#define CP_ASYNC16(saddr, gptr) \
    asm volatile("cp.async.cg.shared.global [%0], [%1], 16;" \
                 :: "r"(saddr), "l"(gptr) : "memory")
#define CP_COMMIT() asm volatile("cp.async.commit_group;" ::: "memory")
#define CP_WAIT0()  asm volatile("cp.async.wait_group 0;" ::: "memory")

// Bijective XOR swizzle within [rows][128] half tile (row stride 256B):
// chunk 0..15 -> (chunk&8) | ((chunk^r)&7); ldmatrix conflict-free.
__device__ __forceinline__ int swz(int r, int k) {
    int c = k >> 3;
    int sc = (c & 8) | ((c ^ r) & 7);
    return r * 128 + sc * 8 + (k & 7);
}

__device__ __forceinline__ int fetch_idx(const void* ei, long long pos, int n) {
    int v;
    if (g_is64) v = (int)((const long long*)ei)[pos];
    else        v = ((const int*)ei)[pos];
    return min(max(v, 0), n - 1);
}

__device__ __forceinline__ uint32_t h2u(__half2 h) {
    return *reinterpret_cast<uint32_t*>(&h);
}

// ---------------------------------------------------------------------------
// Init: build fp16 W^T tiles + dtype detect.  (agg/denom zeroing moved into
// the GEMM, which owns 64 node-rows per block and overlaps the stores.)
// ---------------------------------------------------------------------------
__global__ void k_init(const float* __restrict__ Wl, const float* __restrict__ Wr,
                       const float* __restrict__ Ws,
                       const unsigned int* __restrict__ eiw) {
    if (blockIdx.x == gridDim.x - 1) {           // detect block
        if (threadIdx.x < 32) {
            unsigned int v = 0;
            for (int i = threadIdx.x; i < 128; i += 32) v |= eiw[2 * i + 1];
            v |= __shfl_xor_sync(0xffffffffu, v, 16);
            v |= __shfl_xor_sync(0xffffffffu, v, 8);
            v |= __shfl_xor_sync(0xffffffffu, v, 4);
            v |= __shfl_xor_sync(0xffffffffu, v, 2);
            v |= __shfl_xor_sync(0xffffffffu, v, 1);
            if (threadIdx.x == 0) g_is64 = (v == 0u) ? 1 : 0;
        }
        return;
    }
    int i = blockIdx.x * blockDim.x + threadIdx.x;
    if (i < 3 * 16384) {
        int m = i >> 14, kk = (i >> 7) & 127, nn = i & 127;
        const float* W = (m == 0) ? Wl : ((m == 1) ? Wr : Ws);
        g_Bh16[m * 16384 + swz(nn, kk)] = __float2half(W[kk * 128 + nn]);
    }
}

// ---------------------------------------------------------------------------
// Mixed-precision tensor-core GEMM (+cp.async B prefetch, + zeroing of this
// block's agg/denom rows overlapped with the prologue):
//   which 0/1 (xl, xr):  Ah*Bh;   which 2 (skip): (Ah + Al)*Bh
// ---------------------------------------------------------------------------
#define SM_AH 0
#define SM_AL 16384
#define SM_BH 32768
#define SM_TOTAL 65536

__global__ void __launch_bounds__(256, 3)
k_gemm_mma(const float* __restrict__ x, const float* __restrict__ tf,
           const float* __restrict__ bs, int n) {
    extern __shared__ char smem[];
    const uint32_t sbase = smem_u32(smem);
    const int tid = threadIdx.x;
    const int row0 = blockIdx.x * 64;

    // Prefetch B0 (overlaps with A staging)
    {
        const uint4* gB = reinterpret_cast<const uint4*>(g_Bh16);
        for (int i = tid; i < 2048; i += 256)
            CP_ASYNC16(sbase + SM_BH + i * 16, gB + i);
        CP_COMMIT();
    }

    // Zero this block's agg (64 rows x 256B) and denom (64 rows x 32B)
    {
        const uint4 z4 = make_uint4(0u, 0u, 0u, 0u);
        for (int i = tid; i < 1024; i += 256) {           // 16 uint4 per row
            int r = row0 + (i >> 4);
            if (r < n) reinterpret_cast<uint4*>(g_agg)[r * 16 + (i & 15)] = z4;
        }
        const float4 zf = make_float4(0.f, 0.f, 0.f, 0.f);
        for (int i = tid; i < 128; i += 256) {            // 2 float4 per row
            int r = row0 + (i >> 1);
            if (r < n) reinterpret_cast<float4*>(g_denom)[r * 2 + (i & 1)] = zf;
        }
    }

    // Stage A rows (fp32 coalesced) -> fp16 hi/lo, swizzled
    {
        __half* sh = reinterpret_cast<__half*>(smem + SM_AH);
        __half* sl = reinterpret_cast<__half*>(smem + SM_AL);
        for (int i = tid; i < 64 * 128; i += 256) {
            int r = i >> 7, k = i & 127;
            int g = row0 + r;
            float v = 0.f;
            if (g < n) v = (k < 126) ? x[g * 126 + k] : tf[g * 2 + (k - 126)];
            __half h = __float2half(v);
            int idx = swz(r, k);
            sh[idx] = h;
            sl[idx] = __float2half(v - __half2float(h));
        }
    }
    CP_WAIT0();
    __syncthreads();

    const int wid = tid >> 5;
    const int lane = tid & 31;
    const int wm = wid >> 1;
    const int wn = wid & 1;
    const int r0 = wm * 16;
    const int c0 = wn * 64;
    const int sub = lane >> 3;
    const int rin = lane & 7;

    for (int which = 0; which < 3; which++) {
        float acc[8][4];
#pragma unroll
        for (int nt = 0; nt < 8; nt++)
#pragma unroll
            for (int q = 0; q < 4; q++) acc[nt][q] = 0.f;

        const bool full = (which == 2);
#pragma unroll
        for (int ks = 0; ks < 8; ks++) {
            uint32_t ah[4], al[4];
            {
                const int ar = r0 + (sub & 1) * 8 + rin;
                const int ac = ks * 2 + (sub >> 1);
                const uint32_t off =
                    (uint32_t)(ar * 256 + (((ac & 8) | ((ac ^ ar) & 7)) << 4));
                LDSM_X4(ah[0], ah[1], ah[2], ah[3], sbase + SM_AH + off);
                if (full) LDSM_X4(al[0], al[1], al[2], al[3], sbase + SM_AL + off);
            }
#pragma unroll
            for (int nt2 = 0; nt2 < 4; nt2++) {
                const int br = c0 + nt2 * 16 + (sub >> 1) * 8 + rin;
                const int bc = ks * 2 + (sub & 1);
                const uint32_t off =
                    (uint32_t)(br * 256 + (((bc & 8) | ((bc ^ br) & 7)) << 4));
                uint32_t q0, q1, q2, q3;
                LDSM_X4(q0, q1, q2, q3, sbase + SM_BH + off);
                MMA_F16(acc[nt2 * 2],     ah, q0, q1);
                MMA_F16(acc[nt2 * 2 + 1], ah, q2, q3);
                if (full) {
                    MMA_F16(acc[nt2 * 2],     al, q0, q1);
                    MMA_F16(acc[nt2 * 2 + 1], al, q2, q3);
                }
            }
        }

        __syncthreads();   // all warps done reading B[which]
        if (which < 2) {   // prefetch next B, overlapped with epilogue stores
            const uint4* gB =
                reinterpret_cast<const uint4*>(&g_Bh16[(which + 1) * 16384]);
            for (int i = tid; i < 2048; i += 256)
                CP_ASYNC16(sbase + SM_BH + i * 16, gB + i);
            CP_COMMIT();
        }

        // Epilogue: lane l -> rows r0+(l>>2)(+8), cols c0+nt*8+(l&3)*2
#pragma unroll
        for (int nt = 0; nt < 8; nt++) {
            const int col = c0 + nt * 8 + (lane & 3) * 2;
            const int ra = row0 + r0 + (lane >> 2);
            const int rb = ra + 8;
            if (full) {
                const float b0 = bs[col], b1 = bs[col + 1];
                if (ra < n) {
                    float2 v = make_float2(acc[nt][0] + b0, acc[nt][1] + b1);
                    *reinterpret_cast<float2*>(&g_skip[ra * 128 + col]) = v;
                }
                if (rb < n) {
                    float2 v = make_float2(acc[nt][2] + b0, acc[nt][3] + b1);
                    *reinterpret_cast<float2*>(&g_skip[rb * 128 + col]) = v;
                }
            } else {
                __half2* out_h = (which == 0) ? g_xl : g_xr;
                if (ra < n)
                    out_h[ra * 64 + (col >> 1)] = __floats2half2_rn(acc[nt][0], acc[nt][1]);
                if (rb < n)
                    out_h[rb * 64 + (col >> 1)] = __floats2half2_rn(acc[nt][2], acc[nt][3]);
            }
        }
        if (which < 2) {
            CP_WAIT0();
            __syncthreads();
        }
    }
}

// ---------------------------------------------------------------------------
// Edge score + reduction for one edge.
//   agg:   ONE red.global.add.noftz.v4.f16x2 per lane (8 fp16 channel adds)
//   denom: ee of 4 heads compacted to lanes 0/8, one v4.f32 red (fp32)
// Range safe: |e| <~ 2 measured (R2 rel_err 7e-8 w/o max-sub) => sums << 65504.
// ---------------------------------------------------------------------------
__device__ __forceinline__ void edge_work(const uint4& aU, const uint4& bU,
                                          const float4& t0, const float4& t1,
                                          int lane, int hl, int d) {
    const __half2* ah = reinterpret_cast<const __half2*>(&aU);
    const __half2* bh = reinterpret_cast<const __half2*>(&bU);
    const float2 a01 = __half22float2(ah[0]);
    const float2 a23 = __half22float2(ah[1]);
    const float2 a45 = __half22float2(ah[2]);
    const float2 a67 = __half22float2(ah[3]);
    const float2 b01 = __half22float2(bh[0]);
    const float2 b23 = __half22float2(bh[1]);
    const float2 b45 = __half22float2(bh[2]);
    const float2 b67 = __half22float2(bh[3]);

    float m, p = 0.f;
    m = a01.x + b01.x; p += (m > 0.f ? m : 0.2f * m) * t0.x;
    m = a01.y + b01.y; p += (m > 0.f ? m : 0.2f * m) * t0.y;
    m = a23.x + b23.x; p += (m > 0.f ? m : 0.2f * m) * t0.z;
    m = a23.y + b23.y; p += (m > 0.f ? m : 0.2f * m) * t0.w;
    m = a45.x + b45.x; p += (m > 0.f ? m : 0.2f * m) * t1.x;
    m = a45.y + b45.y; p += (m > 0.f ? m : 0.2f * m) * t1.y;
    m = a67.x + b67.x; p += (m > 0.f ? m : 0.2f * m) * t1.z;
    m = a67.y + b67.y; p += (m > 0.f ? m : 0.2f * m) * t1.w;

    // head h = hl>>1 spans lanes {2h, 2h+1}
    p += __shfl_xor_sync(0xffffffffu, p, 1);

    const float ex = __expf(p);   // softmax-max dropped: |e| bounded

    // Compact ee of 4 heads into lanes hl==0 and hl==8 (per half-warp)
    const int basel = lane & 24;  // 0/8 (+16 for upper half-warp)
    const float v0 = __shfl_sync(0xffffffffu, ex, basel + 0);
    const float v1 = __shfl_sync(0xffffffffu, ex, basel + 2);
    const float v2 = __shfl_sync(0xffffffffu, ex, basel + 4);
    const float v3 = __shfl_sync(0xffffffffu, ex, basel + 6);
    if ((hl & 7) == 0) {
        float* dp = &g_denom[d * 8 + (hl >> 1)];   // hl=0 -> +0, hl=8 -> +4
        asm volatile("red.global.add.v4.f32 [%0], {%1, %2, %3, %4};"
                     :: "l"(dp), "f"(v0), "f"(v1), "f"(v2), "f"(v3) : "memory");
    }

    const uint32_t h0 = h2u(__floats2half2_rn(ex * a01.x, ex * a01.y));
    const uint32_t h1 = h2u(__floats2half2_rn(ex * a23.x, ex * a23.y));
    const uint32_t h2 = h2u(__floats2half2_rn(ex * a45.x, ex * a45.y));
    const uint32_t h3 = h2u(__floats2half2_rn(ex * a67.x, ex * a67.y));
    __half2* p0 = &g_agg[d * 64 + hl * 4];
    asm volatile("red.global.add.noftz.v4.f16x2 [%0], {%1, %2, %3, %4};"
                 :: "l"(p0), "r"(h0), "r"(h1), "r"(h2), "r"(h3) : "memory");
}

// ---------------------------------------------------------------------------
// Fused edge pass: TWO edges per half-warp (4 gathers in flight).
// Real edges only; self-loops handled in k_final.
// ---------------------------------------------------------------------------
__global__ void k_edge(const void* __restrict__ ei,
                       const float* __restrict__ att, int E, int n) {
    const int gt = blockIdx.x * blockDim.x + threadIdx.x;
    const int pair = gt >> 4;
    const int lane = threadIdx.x & 31;
    const int hl = lane & 15;
    const int w0 = pair * 2;
    if (w0 >= E) return;
    const int w1 = w0 + 1;
    const bool has1 = (w1 < E);

    int s0 = fetch_idx(ei, w0, n);
    int d0 = fetch_idx(ei, (long long)E + w0, n);
    int s1 = s0, d1 = d0;
    if (has1) {
        s1 = fetch_idx(ei, w1, n);
        d1 = fetch_idx(ei, (long long)E + w1, n);
    }

    // All four gathers issued back-to-back (MLP = 4 per lane)
    const uint4 a0 = *reinterpret_cast<const uint4*>(&g_xl[s0 * 64 + hl * 4]);
    const uint4 b0 = *reinterpret_cast<const uint4*>(&g_xr[d0 * 64 + hl * 4]);
    const uint4 a1 = *reinterpret_cast<const uint4*>(&g_xl[s1 * 64 + hl * 4]);
    const uint4 b1 = *reinterpret_cast<const uint4*>(&g_xr[d1 * 64 + hl * 4]);

    const float4 t0 = *reinterpret_cast<const float4*>(&att[hl * 8]);
    const float4 t1 = *reinterpret_cast<const float4*>(&att[hl * 8 + 4]);

    edge_work(a0, b0, t0, t1, lane, hl, d0);
    if (has1) edge_work(a1, b1, t0, t1, lane, hl, d1);
}

// ---------------------------------------------------------------------------
// Final: add self-loop contribution (fp32), then
//   out = sigmoid( elu((agg+ee*xl)/(denom+ee) + bias_gat + skip) @ Wo + bo )
// One warp per node; lane covers cols lane*4..+3 (head = lane>>2).
// ---------------------------------------------------------------------------
__global__ void k_final(const float* __restrict__ att,
                        const float* __restrict__ bias_gat,
                        const float* __restrict__ Wo,
                        const float* __restrict__ bo,
                        float* __restrict__ out, int n) {
    const int w = (blockIdx.x * blockDim.x + threadIdx.x) >> 5;
    const int lane = threadIdx.x & 31;
    if (w >= n) return;

    // Self-loop: xl[w], xr[w] (fp16 rows, coalesced)
    const uint2 xlU = *reinterpret_cast<const uint2*>(&g_xl[w * 64 + lane * 2]);
    const uint2 xrU = *reinterpret_cast<const uint2*>(&g_xr[w * 64 + lane * 2]);
    const __half2* xlh = reinterpret_cast<const __half2*>(&xlU);
    const __half2* xrh = reinterpret_cast<const __half2*>(&xrU);
    const float2 xl01 = __half22float2(xlh[0]);
    const float2 xl23 = __half22float2(xlh[1]);
    const float2 xr01 = __half22float2(xrh[0]);
    const float2 xr23 = __half22float2(xrh[1]);
    const float4 at4 = *reinterpret_cast<const float4*>(&att[lane * 4]);

    float m, p2 = 0.f;
    m = xl01.x + xr01.x; p2 += (m > 0.f ? m : 0.2f * m) * at4.x;
    m = xl01.y + xr01.y; p2 += (m > 0.f ? m : 0.2f * m) * at4.y;
    m = xl23.x + xr23.x; p2 += (m > 0.f ? m : 0.2f * m) * at4.z;
    m = xl23.y + xr23.y; p2 += (m > 0.f ? m : 0.2f * m) * at4.w;
    // sum over the head's 16 channels (4-lane group)
    p2 += __shfl_xor_sync(0xffffffffu, p2, 1);
    p2 += __shfl_xor_sync(0xffffffffu, p2, 2);
    const float ee = __expf(p2);

    // agg (fp16) for this lane's 4 channels
    const uint2 gU = *reinterpret_cast<const uint2*>(&g_agg[w * 64 + lane * 2]);
    const __half2* gh = reinterpret_cast<const __half2*>(&gU);
    const float2 g01 = __half22float2(gh[0]);
    const float2 g23 = __half22float2(gh[1]);

    const int base = w * 128 + lane * 4;
    const float4 s  = *reinterpret_cast<const float4*>(&g_skip[base]);
    const float4 bg = *reinterpret_cast<const float4*>(&bias_gat[lane * 4]);
    const float4 ww = *reinterpret_cast<const float4*>(&Wo[lane * 4]);

    const float dn = 1.f / (g_denom[w * 8 + (lane >> 2)] + ee + 1e-16f);

    float c, p = 0.f;
    c = (g01.x + ee * xl01.x) * dn + s.x + bg.x; c = (c > 0.f) ? c : expm1f(c); p += c * ww.x;
    c = (g01.y + ee * xl01.y) * dn + s.y + bg.y; c = (c > 0.f) ? c : expm1f(c); p += c * ww.y;
    c = (g23.x + ee * xl23.x) * dn + s.z + bg.z; c = (c > 0.f) ? c : expm1f(c); p += c * ww.z;
    c = (g23.y + ee * xl23.y) * dn + s.w + bg.w; c = (c > 0.f) ? c : expm1f(c); p += c * ww.w;

    p += __shfl_xor_sync(0xffffffffu, p, 16);
    p += __shfl_xor_sync(0xffffffffu, p, 8);
    p += __shfl_xor_sync(0xffffffffu, p, 4);
    p += __shfl_xor_sync(0xffffffffu, p, 2);
    p += __shfl_xor_sync(0xffffffffu, p, 1);

    if (lane == 0) {
        out[w] = 1.f / (1.f + expf(-(p + bo[0])));
    }
}

// ---------------------------------------------------------------------------
extern "C" void kernel_launch(void* const* d_in, const int* in_sizes, int n_in,
                              void* d_out, int out_size) {
    const float* x   = (const float*)d_in[0];   // [N,126]
    const float* tf  = (const float*)d_in[1];   // [N,2]
    const void*  ei  = d_in[2];                 // [2,E] int32 or int64
    const float* Wl  = (const float*)d_in[3];   // [128,128]
    const float* Wr  = (const float*)d_in[4];
    const float* att = (const float*)d_in[5];   // [8,16]
    const float* bg  = (const float*)d_in[6];   // [128]
    const float* Ws  = (const float*)d_in[7];
    const float* bs  = (const float*)d_in[8];
    const float* Wo  = (const float*)d_in[9];   // [128,1]
    const float* bo  = (const float*)d_in[10];  // [1]
    float* out = (float*)d_out;

    const int n = in_sizes[0] / 126;
    const int E = in_sizes[2] / 2;
    const int pairs = (E + 1) / 2;

    cudaFuncSetAttribute(k_gemm_mma, cudaFuncAttributeMaxDynamicSharedMemorySize,
                         SM_TOTAL);

    k_init<<<(3 * 16384 + 255) / 256 + 1, 256>>>(Wl, Wr, Ws,
                                                 (const unsigned int*)ei);

    k_gemm_mma<<<(n + 63) / 64, 256, SM_TOTAL>>>(x, tf, bs, n);

    k_edge<<<(pairs + 15) / 16, 256>>>(ei, att, E, n);
    k_final<<<(n + 7) / 8, 256>>>(att, bg, Wo, bo, out, n);
}

// round 17
// speedup vs baseline: 2.6980x; 1.1470x over previous
#include <cuda_runtime.h>
#include <cuda_fp16.h>
#include <cstdint>

// Problem constants (shapes are fixed by the dataset)
#define MAX_N 100000
#define MAX_E 1000000

// Scratch: __device__ globals (no runtime allocation allowed)
__device__ __half2 g_xl[MAX_N * 64];     // raw @ Wl   (fp16, 2/word)
__device__ __half2 g_xr[MAX_N * 64];     // raw @ Wr   (fp16)
__device__ __half2 g_skip[MAX_N * 64];   // raw @ Ws + bs  (fp16)
__device__ __align__(16) __half2 g_agg[MAX_N * 64];  // sum(ee*xl[src]), fp16
__device__ float   g_denom[MAX_N * 8];   // softmax denominators (fp32)
__device__ int     g_is64;               // edge_index dtype flag (1 = int64)
// W^T fp16, XOR-swizzled [n][128] layout, 3 matrices
__device__ __half g_Bh16[3 * 128 * 128];

// ===================== PTX helpers (base ISA only) =========================
__device__ __forceinline__ uint32_t smem_u32(const void* p) {
    uint32_t a;
    asm("{ .reg .u64 t; cvta.to.shared.u64 t, %1; cvt.u32.u64 %0, t; }"
        : "=r"(a) : "l"(p));
    return a;
}
#define LDSM_X4(r0, r1, r2, r3, addr) \
    asm volatile("ldmatrix.sync.aligned.m8n8.x4.shared.b16 {%0,%1,%2,%3}, [%4];" \
                 : "=r"(r0), "=r"(r1), "=r"(r2), "=r"(r3) : "r"(addr))
#define MMA_F16(d, a, b0v, b1v) \
    asm volatile("mma.sync.aligned.m16n8k16.row.col.f32.f16.f16.f32 " \
                 "{%0,%1,%2,%3}, {%4,%5,%6,%7}, {%8,%9}, {%0,%1,%2,%3};" \
                 : "+f"((d)[0]), "+f"((d)[1]), "+f"((d)[2]), "+f"((d)[3]) \
                 : "r"((a)[0]), "r"((a)[1]), "r"((a)[2]), "r"((a)[3]), \
                   "r"(b0v), "r"(b1v))
#define CP_ASYNC16(saddr, gptr) \
    asm volatile("cp.async.cg.shared.global [%0], [%1], 16;" \
                 :: "r"(saddr), "l"(gptr) : "memory")
#define CP_COMMIT() asm volatile("cp.async.commit_group;" ::: "memory")
#define CP_WAIT0()  asm volatile("cp.async.wait_group 0;" ::: "memory")

// Bijective XOR swizzle within [rows][128] half tile (row stride 256B):
// chunk 0..15 -> (chunk&8) | ((chunk^r)&7); ldmatrix conflict-free.
__device__ __forceinline__ int swz(int r, int k) {
    int c = k >> 3;
    int sc = (c & 8) | ((c ^ r) & 7);
    return r * 128 + sc * 8 + (k & 7);
}

__device__ __forceinline__ int fetch_idx(const void* ei, long long pos, int n) {
    int v;
    if (g_is64) v = (int)((const long long*)ei)[pos];
    else        v = ((const int*)ei)[pos];
    return min(max(v, 0), n - 1);
}

__device__ __forceinline__ uint32_t h2u(__half2 h) {
    return *reinterpret_cast<uint32_t*>(&h);
}

// ---------------------------------------------------------------------------
// Init: build fp16 W^T tiles + dtype detect.
// ---------------------------------------------------------------------------
__global__ void k_init(const float* __restrict__ Wl, const float* __restrict__ Wr,
                       const float* __restrict__ Ws,
                       const unsigned int* __restrict__ eiw) {
    if (blockIdx.x == gridDim.x - 1) {           // detect block
        if (threadIdx.x < 32) {
            unsigned int v = 0;
            for (int i = threadIdx.x; i < 128; i += 32) v |= eiw[2 * i + 1];
            v |= __shfl_xor_sync(0xffffffffu, v, 16);
            v |= __shfl_xor_sync(0xffffffffu, v, 8);
            v |= __shfl_xor_sync(0xffffffffu, v, 4);
            v |= __shfl_xor_sync(0xffffffffu, v, 2);
            v |= __shfl_xor_sync(0xffffffffu, v, 1);
            if (threadIdx.x == 0) g_is64 = (v == 0u) ? 1 : 0;
        }
        return;
    }
    int i = blockIdx.x * blockDim.x + threadIdx.x;
    if (i < 3 * 16384) {
        int m = i >> 14, kk = (i >> 7) & 127, nn = i & 127;
        const float* W = (m == 0) ? Wl : ((m == 1) ? Wr : Ws);
        g_Bh16[m * 16384 + swz(nn, kk)] = __float2half(W[kk * 128 + nn]);
    }
}

// ---------------------------------------------------------------------------
// fp16 tensor-core GEMM, single product Ah*Bh for all three matrices.
// Block: 64 rows x 128 cols, 256 threads (8 warps = 4m x 2n), A staged once.
// smem 48KB, regs capped 64 -> 4 blocks/SM (32 warps).  cp.async B prefetch.
// Also zeroes this block's agg/denom rows (overlapped with prologue).
// ---------------------------------------------------------------------------
#define SM_AH 0
#define SM_BH 16384
#define SM_TOTAL 49152

__global__ void __launch_bounds__(256, 4)
k_gemm_mma(const float* __restrict__ x, const float* __restrict__ tf,
           const float* __restrict__ bs, int n) {
    extern __shared__ char smem[];
    const uint32_t sbase = smem_u32(smem);
    const int tid = threadIdx.x;
    const int row0 = blockIdx.x * 64;

    // Prefetch B0 (overlaps with A staging)
    {
        const uint4* gB = reinterpret_cast<const uint4*>(g_Bh16);
        for (int i = tid; i < 2048; i += 256)
            CP_ASYNC16(sbase + SM_BH + i * 16, gB + i);
        CP_COMMIT();
    }

    // Zero this block's agg (64 rows x 256B) and denom (64 rows x 32B)
    {
        const uint4 z4 = make_uint4(0u, 0u, 0u, 0u);
        for (int i = tid; i < 1024; i += 256) {           // 16 uint4 per row
            int r = row0 + (i >> 4);
            if (r < n) reinterpret_cast<uint4*>(g_agg)[r * 16 + (i & 15)] = z4;
        }
        const float4 zf = make_float4(0.f, 0.f, 0.f, 0.f);
        for (int i = tid; i < 128; i += 256) {            // 2 float4 per row
            int r = row0 + (i >> 1);
            if (r < n) reinterpret_cast<float4*>(g_denom)[r * 2 + (i & 1)] = zf;
        }
    }

    // Stage A rows (fp32 coalesced) -> fp16, swizzled
    {
        __half* sh = reinterpret_cast<__half*>(smem + SM_AH);
        for (int i = tid; i < 64 * 128; i += 256) {
            int r = i >> 7, k = i & 127;
            int g = row0 + r;
            float v = 0.f;
            if (g < n) v = (k < 126) ? x[g * 126 + k] : tf[g * 2 + (k - 126)];
            sh[swz(r, k)] = __float2half(v);
        }
    }
    CP_WAIT0();
    __syncthreads();

    const int wid = tid >> 5;
    const int lane = tid & 31;
    const int wm = wid >> 1;
    const int wn = wid & 1;
    const int r0 = wm * 16;
    const int c0 = wn * 64;
    const int sub = lane >> 3;
    const int rin = lane & 7;

    for (int which = 0; which < 3; which++) {
        float acc[8][4];
#pragma unroll
        for (int nt = 0; nt < 8; nt++)
#pragma unroll
            for (int q = 0; q < 4; q++) acc[nt][q] = 0.f;

#pragma unroll
        for (int ks = 0; ks < 8; ks++) {
            uint32_t ah[4];
            {
                const int ar = r0 + (sub & 1) * 8 + rin;
                const int ac = ks * 2 + (sub >> 1);
                const uint32_t off =
                    (uint32_t)(ar * 256 + (((ac & 8) | ((ac ^ ar) & 7)) << 4));
                LDSM_X4(ah[0], ah[1], ah[2], ah[3], sbase + SM_AH + off);
            }
#pragma unroll
            for (int nt2 = 0; nt2 < 4; nt2++) {
                const int br = c0 + nt2 * 16 + (sub >> 1) * 8 + rin;
                const int bc = ks * 2 + (sub & 1);
                const uint32_t off =
                    (uint32_t)(br * 256 + (((bc & 8) | ((bc ^ br) & 7)) << 4));
                uint32_t q0, q1, q2, q3;
                LDSM_X4(q0, q1, q2, q3, sbase + SM_BH + off);
                MMA_F16(acc[nt2 * 2],     ah, q0, q1);
                MMA_F16(acc[nt2 * 2 + 1], ah, q2, q3);
            }
        }

        __syncthreads();   // all warps done reading B[which]
        if (which < 2) {   // prefetch next B, overlapped with epilogue stores
            const uint4* gB =
                reinterpret_cast<const uint4*>(&g_Bh16[(which + 1) * 16384]);
            for (int i = tid; i < 2048; i += 256)
                CP_ASYNC16(sbase + SM_BH + i * 16, gB + i);
            CP_COMMIT();
        }

        // Epilogue: lane l -> rows r0+(l>>2)(+8), cols c0+nt*8+(l&3)*2
        __half2* out_h = (which == 0) ? g_xl : ((which == 1) ? g_xr : g_skip);
#pragma unroll
        for (int nt = 0; nt < 8; nt++) {
            const int col = c0 + nt * 8 + (lane & 3) * 2;
            const int ra = row0 + r0 + (lane >> 2);
            const int rb = ra + 8;
            float b0 = 0.f, b1 = 0.f;
            if (which == 2) { b0 = bs[col]; b1 = bs[col + 1]; }
            if (ra < n)
                out_h[ra * 64 + (col >> 1)] =
                    __floats2half2_rn(acc[nt][0] + b0, acc[nt][1] + b1);
            if (rb < n)
                out_h[rb * 64 + (col >> 1)] =
                    __floats2half2_rn(acc[nt][2] + b0, acc[nt][3] + b1);
        }
        if (which < 2) {
            CP_WAIT0();
            __syncthreads();
        }
    }
}

// ---------------------------------------------------------------------------
// Edge score + reduction for one edge.
//   agg:   ONE red.global.add.noftz.v4.f16x2 per lane (8 fp16 channel adds)
//   denom: ee of 4 heads compacted to lanes 0/8, one v4.f32 red (fp32)
// ---------------------------------------------------------------------------
__device__ __forceinline__ void edge_work(const uint4& aU, const uint4& bU,
                                          const float4& t0, const float4& t1,
                                          int lane, int hl, int d) {
    const __half2* ah = reinterpret_cast<const __half2*>(&aU);
    const __half2* bh = reinterpret_cast<const __half2*>(&bU);
    const float2 a01 = __half22float2(ah[0]);
    const float2 a23 = __half22float2(ah[1]);
    const float2 a45 = __half22float2(ah[2]);
    const float2 a67 = __half22float2(ah[3]);
    const float2 b01 = __half22float2(bh[0]);
    const float2 b23 = __half22float2(bh[1]);
    const float2 b45 = __half22float2(bh[2]);
    const float2 b67 = __half22float2(bh[3]);

    float m, p = 0.f;
    m = a01.x + b01.x; p += (m > 0.f ? m : 0.2f * m) * t0.x;
    m = a01.y + b01.y; p += (m > 0.f ? m : 0.2f * m) * t0.y;
    m = a23.x + b23.x; p += (m > 0.f ? m : 0.2f * m) * t0.z;
    m = a23.y + b23.y; p += (m > 0.f ? m : 0.2f * m) * t0.w;
    m = a45.x + b45.x; p += (m > 0.f ? m : 0.2f * m) * t1.x;
    m = a45.y + b45.y; p += (m > 0.f ? m : 0.2f * m) * t1.y;
    m = a67.x + b67.x; p += (m > 0.f ? m : 0.2f * m) * t1.z;
    m = a67.y + b67.y; p += (m > 0.f ? m : 0.2f * m) * t1.w;

    // head h = hl>>1 spans lanes {2h, 2h+1}
    p += __shfl_xor_sync(0xffffffffu, p, 1);

    const float ex = __expf(p);   // softmax-max dropped: |e| bounded

    // Compact ee of 4 heads into lanes hl==0 and hl==8 (per half-warp)
    const int basel = lane & 24;  // 0/8 (+16 for upper half-warp)
    const float v0 = __shfl_sync(0xffffffffu, ex, basel + 0);
    const float v1 = __shfl_sync(0xffffffffu, ex, basel + 2);
    const float v2 = __shfl_sync(0xffffffffu, ex, basel + 4);
    const float v3 = __shfl_sync(0xffffffffu, ex, basel + 6);
    if ((hl & 7) == 0) {
        float* dp = &g_denom[d * 8 + (hl >> 1)];   // hl=0 -> +0, hl=8 -> +4
        asm volatile("red.global.add.v4.f32 [%0], {%1, %2, %3, %4};"
                     :: "l"(dp), "f"(v0), "f"(v1), "f"(v2), "f"(v3) : "memory");
    }

    const uint32_t h0 = h2u(__floats2half2_rn(ex * a01.x, ex * a01.y));
    const uint32_t h1 = h2u(__floats2half2_rn(ex * a23.x, ex * a23.y));
    const uint32_t h2 = h2u(__floats2half2_rn(ex * a45.x, ex * a45.y));
    const uint32_t h3 = h2u(__floats2half2_rn(ex * a67.x, ex * a67.y));
    __half2* p0 = &g_agg[d * 64 + hl * 4];
    asm volatile("red.global.add.noftz.v4.f16x2 [%0], {%1, %2, %3, %4};"
                 :: "l"(p0), "r"(h0), "r"(h1), "r"(h2), "r"(h3) : "memory");
}

// ---------------------------------------------------------------------------
// Fused edge pass: TWO edges per half-warp (4 gathers in flight).
// Real edges only; self-loops handled in k_final.
// ---------------------------------------------------------------------------
__global__ void k_edge(const void* __restrict__ ei,
                       const float* __restrict__ att, int E, int n) {
    const int gt = blockIdx.x * blockDim.x + threadIdx.x;
    const int pair = gt >> 4;
    const int lane = threadIdx.x & 31;
    const int hl = lane & 15;
    const int w0 = pair * 2;
    if (w0 >= E) return;
    const int w1 = w0 + 1;
    const bool has1 = (w1 < E);

    int s0 = fetch_idx(ei, w0, n);
    int d0 = fetch_idx(ei, (long long)E + w0, n);
    int s1 = s0, d1 = d0;
    if (has1) {
        s1 = fetch_idx(ei, w1, n);
        d1 = fetch_idx(ei, (long long)E + w1, n);
    }

    // All four gathers issued back-to-back (MLP = 4 per lane)
    const uint4 a0 = *reinterpret_cast<const uint4*>(&g_xl[s0 * 64 + hl * 4]);
    const uint4 b0 = *reinterpret_cast<const uint4*>(&g_xr[d0 * 64 + hl * 4]);
    const uint4 a1 = *reinterpret_cast<const uint4*>(&g_xl[s1 * 64 + hl * 4]);
    const uint4 b1 = *reinterpret_cast<const uint4*>(&g_xr[d1 * 64 + hl * 4]);

    const float4 t0 = *reinterpret_cast<const float4*>(&att[hl * 8]);
    const float4 t1 = *reinterpret_cast<const float4*>(&att[hl * 8 + 4]);

    edge_work(a0, b0, t0, t1, lane, hl, d0);
    if (has1) edge_work(a1, b1, t0, t1, lane, hl, d1);
}

// ---------------------------------------------------------------------------
// Final: add self-loop contribution (fp32), then
//   out = sigmoid( elu((agg+ee*xl)/(denom+ee) + bias_gat + skip) @ Wo + bo )
// One warp per node; lane covers cols lane*4..+3 (head = lane>>2).
// ---------------------------------------------------------------------------
__global__ void k_final(const float* __restrict__ att,
                        const float* __restrict__ bias_gat,
                        const float* __restrict__ Wo,
                        const float* __restrict__ bo,
                        float* __restrict__ out, int n) {
    const int w = (blockIdx.x * blockDim.x + threadIdx.x) >> 5;
    const int lane = threadIdx.x & 31;
    if (w >= n) return;

    // Self-loop: xl[w], xr[w] (fp16 rows, coalesced)
    const uint2 xlU = *reinterpret_cast<const uint2*>(&g_xl[w * 64 + lane * 2]);
    const uint2 xrU = *reinterpret_cast<const uint2*>(&g_xr[w * 64 + lane * 2]);
    const __half2* xlh = reinterpret_cast<const __half2*>(&xlU);
    const __half2* xrh = reinterpret_cast<const __half2*>(&xrU);
    const float2 xl01 = __half22float2(xlh[0]);
    const float2 xl23 = __half22float2(xlh[1]);
    const float2 xr01 = __half22float2(xrh[0]);
    const float2 xr23 = __half22float2(xrh[1]);
    const float4 at4 = *reinterpret_cast<const float4*>(&att[lane * 4]);

    float m, p2 = 0.f;
    m = xl01.x + xr01.x; p2 += (m > 0.f ? m : 0.2f * m) * at4.x;
    m = xl01.y + xr01.y; p2 += (m > 0.f ? m : 0.2f * m) * at4.y;
    m = xl23.x + xr23.x; p2 += (m > 0.f ? m : 0.2f * m) * at4.z;
    m = xl23.y + xr23.y; p2 += (m > 0.f ? m : 0.2f * m) * at4.w;
    // sum over the head's 16 channels (4-lane group)
    p2 += __shfl_xor_sync(0xffffffffu, p2, 1);
    p2 += __shfl_xor_sync(0xffffffffu, p2, 2);
    const float ee = __expf(p2);

    // agg (fp16) for this lane's 4 channels
    const uint2 gU = *reinterpret_cast<const uint2*>(&g_agg[w * 64 + lane * 2]);
    const __half2* gh = reinterpret_cast<const __half2*>(&gU);
    const float2 g01 = __half22float2(gh[0]);
    const float2 g23 = __half22float2(gh[1]);

    // skip (fp16) for this lane's 4 channels
    const uint2 sU = *reinterpret_cast<const uint2*>(&g_skip[w * 64 + lane * 2]);
    const __half2* sh = reinterpret_cast<const __half2*>(&sU);
    const float2 s01 = __half22float2(sh[0]);
    const float2 s23 = __half22float2(sh[1]);

    const float4 bg = *reinterpret_cast<const float4*>(&bias_gat[lane * 4]);
    const float4 ww = *reinterpret_cast<const float4*>(&Wo[lane * 4]);

    const float dn = 1.f / (g_denom[w * 8 + (lane >> 2)] + ee + 1e-16f);

    float c, p = 0.f;
    c = (g01.x + ee * xl01.x) * dn + s01.x + bg.x; c = (c > 0.f) ? c : expm1f(c); p += c * ww.x;
    c = (g01.y + ee * xl01.y) * dn + s01.y + bg.y; c = (c > 0.f) ? c : expm1f(c); p += c * ww.y;
    c = (g23.x + ee * xl23.x) * dn + s23.x + bg.z; c = (c > 0.f) ? c : expm1f(c); p += c * ww.z;
    c = (g23.y + ee * xl23.y) * dn + s23.y + bg.w; c = (c > 0.f) ? c : expm1f(c); p += c * ww.w;

    p += __shfl_xor_sync(0xffffffffu, p, 16);
    p += __shfl_xor_sync(0xffffffffu, p, 8);
    p += __shfl_xor_sync(0xffffffffu, p, 4);
    p += __shfl_xor_sync(0xffffffffu, p, 2);
    p += __shfl_xor_sync(0xffffffffu, p, 1);

    if (lane == 0) {
        out[w] = 1.f / (1.f + expf(-(p + bo[0])));
    }
}

// ---------------------------------------------------------------------------
extern "C" void kernel_launch(void* const* d_in, const int* in_sizes, int n_in,
                              void* d_out, int out_size) {
    const float* x   = (const float*)d_in[0];   // [N,126]
    const float* tf  = (const float*)d_in[1];   // [N,2]
    const void*  ei  = d_in[2];                 // [2,E] int32 or int64
    const float* Wl  = (const float*)d_in[3];   // [128,128]
    const float* Wr  = (const float*)d_in[4];
    const float* att = (const float*)d_in[5];   // [8,16]
    const float* bg  = (const float*)d_in[6];   // [128]
    const float* Ws  = (const float*)d_in[7];
    const float* bs  = (const float*)d_in[8];
    const float* Wo  = (const float*)d_in[9];   // [128,1]
    const float* bo  = (const float*)d_in[10];  // [1]
    float* out = (float*)d_out;

    const int n = in_sizes[0] / 126;
    const int E = in_sizes[2] / 2;
    const int pairs = (E + 1) / 2;

    cudaFuncSetAttribute(k_gemm_mma, cudaFuncAttributeMaxDynamicSharedMemorySize,
                         SM_TOTAL);

    k_init<<<(3 * 16384 + 255) / 256 + 1, 256>>>(Wl, Wr, Ws,
                                                 (const unsigned int*)ei);

    k_gemm_mma<<<(n + 63) / 64, 256, SM_TOTAL>>>(x, tf, bs, n);

    k_edge<<<(pairs + 15) / 16, 256>>>(ei, att, E, n);
    k_final<<<(n + 7) / 8, 256>>>(att, bg, Wo, bo, out, n);
}